// round 8
// baseline (speedup 1.0000x reference)
#include <cuda_runtime.h>
#include <cuda_bf16.h>
#include <mma.h>
#include <cuda_pipeline.h>
#include <cstdint>

using namespace nvcuda;

// ---------------------------------------------------------------------------
// JKNet R8: aggregation fused into GEMM prologue. Each 64-row GEMM tile
// gathers its own rows from the previous layer's h (global), dn-folds,
// splits bf16 hi/lo into smem, and runs the 3-pass wmma GEMM.
// Dual-mode gather streams plain sums to F for the fused K=384 output GEMM,
// whose 3rd segment computes F2 = plain agg(h2) inline. No A buffer at all.
// ---------------------------------------------------------------------------

#define NN 50000
#define EE 800000
#define DD 128

// ---------------- scratch ---------------------------------------------------
__device__ float g_h0[NN * DD];
__device__ float g_h1[NN * DD];
__device__ float g_h2[NN * DD];
__device__ float g_F0[NN * DD];
__device__ float g_F1[NN * DD];
__device__ float g_srcn[NN];
__device__ float g_dstn[NN];
__device__ int   g_outdeg[NN];
__device__ int   g_indeg [NN];
__device__ int   g_rowptr[NN + 1];
__device__ int   g_cursor[NN];
__device__ int   g_colidx[EE];
__device__ int   g_bsum[256];
__device__ __nv_bfloat16 g_Bhi[6 * DD * DD];
__device__ __nv_bfloat16 g_Blo[6 * DD * DD];

// ---------------- CSR build -------------------------------------------------
__global__ void zero_ints(int* __restrict__ a, int* __restrict__ b, int n) {
    int i = blockIdx.x * blockDim.x + threadIdx.x;
    if (i < n) { a[i] = 0; b[i] = 0; }
}
__global__ void deg_hist(const int* __restrict__ src, const int* __restrict__ dst,
                         int* __restrict__ outdeg, int* __restrict__ indeg, int e) {
    int i = blockIdx.x * blockDim.x + threadIdx.x;
    if (i < e) { atomicAdd(&outdeg[src[i]], 1); atomicAdd(&indeg[dst[i]], 1); }
}
__global__ void scan_block_sums(const int* __restrict__ deg, int* __restrict__ bsum, int n) {
    __shared__ int s[256];
    int i = blockIdx.x * 256 + threadIdx.x;
    s[threadIdx.x] = (i < n) ? deg[i] : 0;
    __syncthreads();
    for (int off = 128; off > 0; off >>= 1) {
        if (threadIdx.x < off) s[threadIdx.x] += s[threadIdx.x + off];
        __syncthreads();
    }
    if (threadIdx.x == 0) bsum[blockIdx.x] = s[0];
}
__global__ void scan_bsums(int* __restrict__ bsum, int nb) {
    __shared__ int s[256];
    int t = threadIdx.x;
    int v = (t < nb) ? bsum[t] : 0;
    s[t] = v;
    __syncthreads();
    for (int off = 1; off < 256; off <<= 1) {
        int add = (t >= off) ? s[t - off] : 0;
        __syncthreads();
        s[t] += add;
        __syncthreads();
    }
    if (t < nb) bsum[t] = s[t] - v;
}
__global__ void scan_final(const int* __restrict__ deg, const int* __restrict__ bsum,
                           const int* __restrict__ outdeg,
                           int* __restrict__ rowptr, int* __restrict__ cursor,
                           float* __restrict__ sn, float* __restrict__ dn,
                           int n, int etot) {
    __shared__ int s[256];
    int t = threadIdx.x;
    int i = blockIdx.x * 256 + t;
    int v = (i < n) ? deg[i] : 0;
    s[t] = v;
    __syncthreads();
    for (int off = 1; off < 256; off <<= 1) {
        int add = (t >= off) ? s[t - off] : 0;
        __syncthreads();
        s[t] += add;
        __syncthreads();
    }
    int ex = bsum[blockIdx.x] + s[t] - v;
    if (i < n) {
        rowptr[i] = ex;
        cursor[i] = ex;
        sn[i] = rsqrtf((float)max(outdeg[i], 1));
        dn[i] = rsqrtf((float)max(v, 1));
    }
    if (i == 0) rowptr[n] = etot;
}
__global__ void scatter_edges(const int* __restrict__ src, const int* __restrict__ dst,
                              int* __restrict__ cursor, int* __restrict__ colidx, int e) {
    int i = blockIdx.x * blockDim.x + threadIdx.x;
    if (i < e) {
        int p = atomicAdd(&cursor[dst[i]], 1);
        colidx[p] = src[i];
    }
}

// ---------------- W conversion ----------------------------------------------
__global__ void conv_w(const float* __restrict__ W0, const float* __restrict__ W1,
                       const float* __restrict__ W2, const float* __restrict__ Wout,
                       __nv_bfloat16* __restrict__ hi, __nv_bfloat16* __restrict__ lo) {
    int idx = blockIdx.x * blockDim.x + threadIdx.x;
    if (idx >= 6 * DD * DD) return;
    int m = idx / (DD * DD);
    int rem = idx % (DD * DD);
    const float* src = (m == 0) ? W0 : (m == 1) ? W1 : (m == 2) ? W2
                                     : (Wout + (m - 3) * DD * DD);
    float v = src[rem];
    __nv_bfloat16 h = __float2bfloat16(v);
    __nv_bfloat16 l = __float2bfloat16(v - __bfloat162float(h));
    hi[idx] = h;
    lo[idx] = l;
}

// ---------------- shared GEMM pieces ----------------------------------------
#define ALD 136
#define BLD 136
#define SM_AHI 0
#define SM_ALO 17408
#define SM_BHI 34816
#define SM_BLO 69632
#define SM_BIAS 104448
#define SM_TOT 112640

// stage a gathered fp32 row-accumulator (128 cols across 32 lanes as float4)
// into the hi/lo bf16 smem images at tile-local row `local`.
__device__ __forceinline__ void split_store_row(__nv_bfloat16* sAhi, __nv_bfloat16* sAlo,
                                                int local, int lane, float4 v) {
    __nv_bfloat16 h0 = __float2bfloat16(v.x);
    __nv_bfloat16 h1 = __float2bfloat16(v.y);
    __nv_bfloat16 h2 = __float2bfloat16(v.z);
    __nv_bfloat16 h3 = __float2bfloat16(v.w);
    __nv_bfloat16 l0 = __float2bfloat16(v.x - __bfloat162float(h0));
    __nv_bfloat16 l1 = __float2bfloat16(v.y - __bfloat162float(h1));
    __nv_bfloat16 l2 = __float2bfloat16(v.z - __bfloat162float(h2));
    __nv_bfloat16 l3 = __float2bfloat16(v.w - __bfloat162float(h3));
    __nv_bfloat16* dh = sAhi + local * ALD + lane * 4;
    __nv_bfloat16* dl = sAlo + local * ALD + lane * 4;
    dh[0] = h0; dh[1] = h1; dh[2] = h2; dh[3] = h3;
    dl[0] = l0; dl[1] = l1; dl[2] = l2; dl[3] = l3;
}

// gather one node row: scaled sum into *vS; if WANTP, plain sum into *vP.
template <bool WANTS, bool WANTP>
__device__ __forceinline__ void gather_row(const float4* __restrict__ X4,
                                           const int* __restrict__ colidx,
                                           const float* __restrict__ srcn,
                                           int beg, int end, int lane,
                                           float4* vS, float4* vP) {
    float4 aS = make_float4(0.f, 0.f, 0.f, 0.f);
    float4 aP = make_float4(0.f, 0.f, 0.f, 0.f);
    int e = beg;
    for (; e + 3 < end; e += 4) {
        int s0 = colidx[e], s1 = colidx[e + 1];
        int s2 = colidx[e + 2], s3 = colidx[e + 3];
        float4 v0 = X4[s0 * 32 + lane];
        float4 v1 = X4[s1 * 32 + lane];
        float4 v2 = X4[s2 * 32 + lane];
        float4 v3 = X4[s3 * 32 + lane];
        if (WANTS) {
            float n0 = srcn[s0], n1 = srcn[s1], n2 = srcn[s2], n3 = srcn[s3];
            aS.x += v0.x * n0 + v1.x * n1 + v2.x * n2 + v3.x * n3;
            aS.y += v0.y * n0 + v1.y * n1 + v2.y * n2 + v3.y * n3;
            aS.z += v0.z * n0 + v1.z * n1 + v2.z * n2 + v3.z * n3;
            aS.w += v0.w * n0 + v1.w * n1 + v2.w * n2 + v3.w * n3;
        }
        if (WANTP) {
            aP.x += v0.x + v1.x + v2.x + v3.x;
            aP.y += v0.y + v1.y + v2.y + v3.y;
            aP.z += v0.z + v1.z + v2.z + v3.z;
            aP.w += v0.w + v1.w + v2.w + v3.w;
        }
    }
    for (; e < end; e++) {
        int s0 = colidx[e];
        float4 v0 = X4[s0 * 32 + lane];
        if (WANTS) {
            float n0 = srcn[s0];
            aS.x += v0.x * n0; aS.y += v0.y * n0; aS.z += v0.z * n0; aS.w += v0.w * n0;
        }
        if (WANTP) { aP.x += v0.x; aP.y += v0.y; aP.z += v0.z; aP.w += v0.w; }
    }
    *vS = aS;
    *vP = aP;
}

// ---------------- fused conv layer: H = relu((agg_s(X))@W*dn + b) -----------
// HASP: also write plain agg to Fout.
template <bool HASP>
__global__ void __launch_bounds__(256, 2)
conv_gemm(const float* __restrict__ X,
          const int* __restrict__ rowptr, const int* __restrict__ colidx,
          const float* __restrict__ srcn, const float* __restrict__ dstn,
          const __nv_bfloat16* __restrict__ Bh, const __nv_bfloat16* __restrict__ Bl,
          const float* __restrict__ bias,
          float* __restrict__ H, float* __restrict__ Fout, int n) {
    extern __shared__ unsigned char smem[];
    __nv_bfloat16* sAhi = (__nv_bfloat16*)(smem + SM_AHI);
    __nv_bfloat16* sAlo = (__nv_bfloat16*)(smem + SM_ALO);
    __nv_bfloat16* sBhi = (__nv_bfloat16*)(smem + SM_BHI);
    __nv_bfloat16* sBlo = (__nv_bfloat16*)(smem + SM_BLO);
    float*         sBias = (float*)(smem + SM_BIAS);

    const int tid  = threadIdx.x;
    const int wid  = tid >> 5;
    const int lane = tid & 31;
    const int row0 = blockIdx.x * 64;

    // B async copy first — overlaps the whole gather.
#pragma unroll
    for (int i = 0; i < 8; i++) {
        int idx = i * 256 + tid;
        int r   = idx >> 4;
        int c16 = idx & 15;
        __pipeline_memcpy_async(sBhi + r * BLD + c16 * 8, Bh + r * 128 + c16 * 8, 16);
        __pipeline_memcpy_async(sBlo + r * BLD + c16 * 8, Bl + r * 128 + c16 * 8, 16);
    }
    __pipeline_commit();

    for (int idx = tid; idx < 2048; idx += 256)
        sBias[idx] = bias[(idx >> 8) * 16 + (idx & 15)];

    // gather: warp w owns tile-local rows w*8..w*8+7
    const float4* X4 = (const float4*)X;
#pragma unroll
    for (int i = 0; i < 8; i++) {
        int local = wid * 8 + i;
        int r = row0 + local;
        float4 vS = make_float4(0.f, 0.f, 0.f, 0.f), vP;
        if (r < n) {
            gather_row<true, HASP>(X4, colidx, srcn, rowptr[r], rowptr[r + 1],
                                   lane, &vS, &vP);
            if (HASP) ((float4*)Fout)[r * 32 + lane] = vP;
            float dn = dstn[r];
            vS.x *= dn; vS.y *= dn; vS.z *= dn; vS.w *= dn;
        }
        split_store_row(sAhi, sAlo, local, lane, vS);
    }
    __pipeline_wait_prior(0);
    __syncthreads();

    const int rt = wid >> 1;
    const int ch = wid & 1;
    wmma::fragment<wmma::accumulator, 16, 16, 16, float> acc[4];
#pragma unroll
    for (int j = 0; j < 4; j++)
        wmma::load_matrix_sync(acc[j], sBias + (ch * 4 + j) * 256, 16, wmma::mem_row_major);

#pragma unroll
    for (int kk = 0; kk < 8; kk++) {
        wmma::fragment<wmma::matrix_a, 16, 16, 16, __nv_bfloat16, wmma::row_major> ah, al;
        wmma::load_matrix_sync(ah, sAhi + (rt * 16) * ALD + kk * 16, ALD);
        wmma::load_matrix_sync(al, sAlo + (rt * 16) * ALD + kk * 16, ALD);
#pragma unroll
        for (int j = 0; j < 4; j++) {
            int nt = ch * 4 + j;
            wmma::fragment<wmma::matrix_b, 16, 16, 16, __nv_bfloat16, wmma::row_major> bh, bl;
            wmma::load_matrix_sync(bh, sBhi + (kk * 16) * BLD + nt * 16, BLD);
            wmma::load_matrix_sync(bl, sBlo + (kk * 16) * BLD + nt * 16, BLD);
            wmma::mma_sync(acc[j], ah, bh, acc[j]);
            wmma::mma_sync(acc[j], ah, bl, acc[j]);
            wmma::mma_sync(acc[j], al, bh, acc[j]);
        }
    }

    if (row0 + rt * 16 + 16 <= n) {
#pragma unroll
        for (int j = 0; j < 4; j++) {
#pragma unroll
            for (int i = 0; i < acc[j].num_elements; i++)
                acc[j].x[i] = fmaxf(acc[j].x[i], 0.f);
            wmma::store_matrix_sync(H + (size_t)(row0 + rt * 16) * 128 + (ch * 4 + j) * 16,
                                    acc[j], 128, wmma::mem_row_major);
        }
    }
}

// ---------------- fused output GEMM: out = [F0 F1 aggP(h2)] @ Wout + bout ---
__global__ void __launch_bounds__(256, 2)
final_gemm(const float* __restrict__ F0, const float* __restrict__ F1,
           const float* __restrict__ h2,
           const int* __restrict__ rowptr, const int* __restrict__ colidx,
           const __nv_bfloat16* __restrict__ Bh3, const __nv_bfloat16* __restrict__ Bl3,
           const float* __restrict__ bias,
           float* __restrict__ C, int n) {
    extern __shared__ unsigned char smem[];
    __nv_bfloat16* sAhi = (__nv_bfloat16*)(smem + SM_AHI);
    __nv_bfloat16* sAlo = (__nv_bfloat16*)(smem + SM_ALO);
    __nv_bfloat16* sBhi = (__nv_bfloat16*)(smem + SM_BHI);
    __nv_bfloat16* sBlo = (__nv_bfloat16*)(smem + SM_BLO);
    float*         sBias = (float*)(smem + SM_BIAS);

    const int tid  = threadIdx.x;
    const int wid  = tid >> 5;
    const int lane = tid & 31;
    const int row0 = blockIdx.x * 64;

    for (int idx = tid; idx < 2048; idx += 256)
        sBias[idx] = bias[(idx >> 8) * 16 + (idx & 15)];
    __syncthreads();

    const int rt = wid >> 1;
    const int ch = wid & 1;
    wmma::fragment<wmma::accumulator, 16, 16, 16, float> acc[4];
#pragma unroll
    for (int j = 0; j < 4; j++)
        wmma::load_matrix_sync(acc[j], sBias + (ch * 4 + j) * 256, 16, wmma::mem_row_major);

    const float* Fs[2] = {F0, F1};
#pragma unroll
    for (int seg = 0; seg < 3; seg++) {
        if (seg > 0) __syncthreads();
        // B segment async copy
        const __nv_bfloat16* Bh = Bh3 + seg * DD * DD;
        const __nv_bfloat16* Bl = Bl3 + seg * DD * DD;
#pragma unroll
        for (int i = 0; i < 8; i++) {
            int idx = i * 256 + tid;
            int r   = idx >> 4;
            int c16 = idx & 15;
            __pipeline_memcpy_async(sBhi + r * BLD + c16 * 8, Bh + r * 128 + c16 * 8, 16);
            __pipeline_memcpy_async(sBlo + r * BLD + c16 * 8, Bl + r * 128 + c16 * 8, 16);
        }
        __pipeline_commit();

        if (seg < 2) {
            // stage F seg from global fp32
            const float* Ap = Fs[seg];
#pragma unroll
            for (int i = 0; i < 8; i++) {
                int idx4 = i * 256 + tid;
                int row  = idx4 >> 5;
                int c4   = idx4 & 31;
                float4 v = make_float4(0.f, 0.f, 0.f, 0.f);
                if (row0 + row < n)
                    v = *(const float4*)(Ap + (size_t)(row0 + row) * 128 + c4 * 4);
                // reuse split_store (c4 plays the role of lane here: cols c4*4..+3)
                split_store_row(sAhi, sAlo, row, c4, v);
            }
        } else {
            // compute F2 rows inline: plain agg of h2
            const float4* X4 = (const float4*)h2;
#pragma unroll
            for (int i = 0; i < 8; i++) {
                int local = wid * 8 + i;
                int r = row0 + local;
                float4 vS, vP = make_float4(0.f, 0.f, 0.f, 0.f);
                if (r < n)
                    gather_row<false, true>(X4, colidx, nullptr, rowptr[r], rowptr[r + 1],
                                            lane, &vS, &vP);
                split_store_row(sAhi, sAlo, local, lane, vP);
            }
        }
        __pipeline_wait_prior(0);
        __syncthreads();

#pragma unroll
        for (int kk = 0; kk < 8; kk++) {
            wmma::fragment<wmma::matrix_a, 16, 16, 16, __nv_bfloat16, wmma::row_major> ah, al;
            wmma::load_matrix_sync(ah, sAhi + (rt * 16) * ALD + kk * 16, ALD);
            wmma::load_matrix_sync(al, sAlo + (rt * 16) * ALD + kk * 16, ALD);
#pragma unroll
            for (int j = 0; j < 4; j++) {
                int nt = ch * 4 + j;
                wmma::fragment<wmma::matrix_b, 16, 16, 16, __nv_bfloat16, wmma::row_major> bh, bl;
                wmma::load_matrix_sync(bh, sBhi + (kk * 16) * BLD + nt * 16, BLD);
                wmma::load_matrix_sync(bl, sBlo + (kk * 16) * BLD + nt * 16, BLD);
                wmma::mma_sync(acc[j], ah, bh, acc[j]);
                wmma::mma_sync(acc[j], ah, bl, acc[j]);
                wmma::mma_sync(acc[j], al, bh, acc[j]);
            }
        }
    }

    if (row0 + rt * 16 + 16 <= n) {
#pragma unroll
        for (int j = 0; j < 4; j++)
            wmma::store_matrix_sync(C + (size_t)(row0 + rt * 16) * 128 + (ch * 4 + j) * 16,
                                    acc[j], 128, wmma::mem_row_major);
    }
}

// ---------------------------------------------------------------------------
extern "C" void kernel_launch(void* const* d_in, const int* in_sizes, int n_in,
                              void* d_out, int out_size) {
    const float* feats = (const float*)d_in[0];
    const int*   src   = (const int*)  d_in[1];
    const int*   dst   = (const int*)  d_in[2];
    const float* W0    = (const float*)d_in[3];
    const float* b0    = (const float*)d_in[4];
    const float* W1    = (const float*)d_in[5];
    const float* b1    = (const float*)d_in[6];
    const float* W2    = (const float*)d_in[7];
    const float* b2    = (const float*)d_in[8];
    const float* Wout  = (const float*)d_in[9];
    const float* bout  = (const float*)d_in[10];
    float*       out   = (float*)d_out;

    const int n = in_sizes[0] / DD;
    const int e = in_sizes[1];

    float *F0, *F1, *h0, *h1, *h2, *srcn, *dstn;
    int *outdeg, *indeg, *rowptr, *cursor, *colidx, *bsum;
    __nv_bfloat16 *Bhi, *Blo;
    cudaGetSymbolAddress((void**)&F0,     g_F0);
    cudaGetSymbolAddress((void**)&F1,     g_F1);
    cudaGetSymbolAddress((void**)&h0,     g_h0);
    cudaGetSymbolAddress((void**)&h1,     g_h1);
    cudaGetSymbolAddress((void**)&h2,     g_h2);
    cudaGetSymbolAddress((void**)&srcn,   g_srcn);
    cudaGetSymbolAddress((void**)&dstn,   g_dstn);
    cudaGetSymbolAddress((void**)&outdeg, g_outdeg);
    cudaGetSymbolAddress((void**)&indeg,  g_indeg);
    cudaGetSymbolAddress((void**)&rowptr, g_rowptr);
    cudaGetSymbolAddress((void**)&cursor, g_cursor);
    cudaGetSymbolAddress((void**)&colidx, g_colidx);
    cudaGetSymbolAddress((void**)&bsum,   g_bsum);
    cudaGetSymbolAddress((void**)&Bhi,    g_Bhi);
    cudaGetSymbolAddress((void**)&Blo,    g_Blo);

    const int nbN = (n + 255) / 256;
    const int nbE = (e + 255) / 256;
    const int nbT = (n + 63) / 64;      // 782 tiles

    cudaFuncSetAttribute(conv_gemm<false>, cudaFuncAttributeMaxDynamicSharedMemorySize, SM_TOT);
    cudaFuncSetAttribute(conv_gemm<true>,  cudaFuncAttributeMaxDynamicSharedMemorySize, SM_TOT);
    cudaFuncSetAttribute(final_gemm,       cudaFuncAttributeMaxDynamicSharedMemorySize, SM_TOT);

    // ---- CSR build + norms + weight conversion ----
    zero_ints      <<<nbN, 256>>>(outdeg, indeg, n);
    conv_w         <<<(6 * DD * DD + 255) / 256, 256>>>(W0, W1, W2, Wout, Bhi, Blo);
    deg_hist       <<<nbE, 256>>>(src, dst, outdeg, indeg, e);
    scan_block_sums<<<nbN, 256>>>(indeg, bsum, n);
    scan_bsums     <<<1,   256>>>(bsum, nbN);
    scan_final     <<<nbN, 256>>>(indeg, bsum, outdeg, rowptr, cursor, srcn, dstn, n, e);
    scatter_edges  <<<nbE, 256>>>(src, dst, cursor, colidx, e);

    // ---- fused layers ----
    conv_gemm<false><<<nbT, 256, SM_TOT>>>(feats, rowptr, colidx, srcn, dstn,
                                           Bhi + 0 * DD * DD, Blo + 0 * DD * DD,
                                           b0, h0, nullptr, n);
    conv_gemm<true> <<<nbT, 256, SM_TOT>>>(h0, rowptr, colidx, srcn, dstn,
                                           Bhi + 1 * DD * DD, Blo + 1 * DD * DD,
                                           b1, h1, F0, n);
    conv_gemm<true> <<<nbT, 256, SM_TOT>>>(h1, rowptr, colidx, srcn, dstn,
                                           Bhi + 2 * DD * DD, Blo + 2 * DD * DD,
                                           b2, h2, F1, n);
    final_gemm      <<<nbT, 256, SM_TOT>>>(F0, F1, h2, rowptr, colidx,
                                           Bhi + 3 * DD * DD, Blo + 3 * DD * DD,
                                           bout, out, n);
}

// round 9
// speedup vs baseline: 1.2720x; 1.2720x over previous
#include <cuda_runtime.h>
#include <cuda_bf16.h>
#include <mma.h>
#include <cuda_pipeline.h>
#include <cstdint>

using namespace nvcuda;

// ---------------------------------------------------------------------------
// JKNet R9: R7 structure (separate agg / GEMM kernels — R8 fusion regressed),
// but agg now emits dn-folded bf16 hi/lo split images directly, so the GEMM
// prologue is pure cp.async for A and B. Math identical to R7 (3-pass split).
// ---------------------------------------------------------------------------

#define NN 50000
#define EE 800000
#define DD 128
#define NPAD (NN + 64)   // pad A/F images so OOB tile rows stay in-bounds

// ---------------- scratch ---------------------------------------------------
__device__ float g_h0[NN * DD];
__device__ float g_h1[NN * DD];
__device__ float g_h2[NN * DD];
__device__ __nv_bfloat16 g_Ahi[NPAD * DD];
__device__ __nv_bfloat16 g_Alo[NPAD * DD];
__device__ __nv_bfloat16 g_Fhi[3][NPAD * DD];
__device__ __nv_bfloat16 g_Flo[3][NPAD * DD];
__device__ float g_srcn[NN];
__device__ float g_dstn[NN];
__device__ int   g_outdeg[NN];
__device__ int   g_indeg [NN];
__device__ int   g_rowptr[NN + 1];
__device__ int   g_cursor[NN];
__device__ int   g_colidx[EE];
__device__ int   g_bsum[256];
__device__ __nv_bfloat16 g_Bhi[6 * DD * DD];
__device__ __nv_bfloat16 g_Blo[6 * DD * DD];

// ---------------- CSR build -------------------------------------------------
__global__ void zero_ints(int* __restrict__ a, int* __restrict__ b, int n) {
    int i = blockIdx.x * blockDim.x + threadIdx.x;
    if (i < n) { a[i] = 0; b[i] = 0; }
}
__global__ void deg_hist(const int* __restrict__ src, const int* __restrict__ dst,
                         int* __restrict__ outdeg, int* __restrict__ indeg, int e) {
    int i = blockIdx.x * blockDim.x + threadIdx.x;
    if (i < e) { atomicAdd(&outdeg[src[i]], 1); atomicAdd(&indeg[dst[i]], 1); }
}
__global__ void scan_block_sums(const int* __restrict__ deg, int* __restrict__ bsum, int n) {
    __shared__ int s[256];
    int i = blockIdx.x * 256 + threadIdx.x;
    s[threadIdx.x] = (i < n) ? deg[i] : 0;
    __syncthreads();
    for (int off = 128; off > 0; off >>= 1) {
        if (threadIdx.x < off) s[threadIdx.x] += s[threadIdx.x + off];
        __syncthreads();
    }
    if (threadIdx.x == 0) bsum[blockIdx.x] = s[0];
}
__global__ void scan_bsums(int* __restrict__ bsum, int nb) {
    __shared__ int s[256];
    int t = threadIdx.x;
    int v = (t < nb) ? bsum[t] : 0;
    s[t] = v;
    __syncthreads();
    for (int off = 1; off < 256; off <<= 1) {
        int add = (t >= off) ? s[t - off] : 0;
        __syncthreads();
        s[t] += add;
        __syncthreads();
    }
    if (t < nb) bsum[t] = s[t] - v;
}
__global__ void scan_final(const int* __restrict__ deg, const int* __restrict__ bsum,
                           const int* __restrict__ outdeg,
                           int* __restrict__ rowptr, int* __restrict__ cursor,
                           float* __restrict__ sn, float* __restrict__ dn,
                           int n, int etot) {
    __shared__ int s[256];
    int t = threadIdx.x;
    int i = blockIdx.x * 256 + t;
    int v = (i < n) ? deg[i] : 0;
    s[t] = v;
    __syncthreads();
    for (int off = 1; off < 256; off <<= 1) {
        int add = (t >= off) ? s[t - off] : 0;
        __syncthreads();
        s[t] += add;
        __syncthreads();
    }
    int ex = bsum[blockIdx.x] + s[t] - v;
    if (i < n) {
        rowptr[i] = ex;
        cursor[i] = ex;
        sn[i] = rsqrtf((float)max(outdeg[i], 1));
        dn[i] = rsqrtf((float)max(v, 1));
    }
    if (i == 0) rowptr[n] = etot;
}
__global__ void scatter_edges(const int* __restrict__ src, const int* __restrict__ dst,
                              int* __restrict__ cursor, int* __restrict__ colidx, int e) {
    int i = blockIdx.x * blockDim.x + threadIdx.x;
    if (i < e) {
        int p = atomicAdd(&cursor[dst[i]], 1);
        colidx[p] = src[i];
    }
}

// ---------------- W conversion ----------------------------------------------
__global__ void conv_w(const float* __restrict__ W0, const float* __restrict__ W1,
                       const float* __restrict__ W2, const float* __restrict__ Wout,
                       __nv_bfloat16* __restrict__ hi, __nv_bfloat16* __restrict__ lo) {
    int idx = blockIdx.x * blockDim.x + threadIdx.x;
    if (idx >= 6 * DD * DD) return;
    int m = idx / (DD * DD);
    int rem = idx % (DD * DD);
    const float* src = (m == 0) ? W0 : (m == 1) ? W1 : (m == 2) ? W2
                                     : (Wout + (m - 3) * DD * DD);
    float v = src[rem];
    __nv_bfloat16 h = __float2bfloat16(v);
    __nv_bfloat16 l = __float2bfloat16(v - __bfloat162float(h));
    hi[idx] = h;
    lo[idx] = l;
}

// split a float4 (cols lane*4..+3 of row r) into bf16 hi/lo images
__device__ __forceinline__ void split_store(__nv_bfloat16* __restrict__ hi,
                                            __nv_bfloat16* __restrict__ lo,
                                            int r, int lane, float4 v) {
    __nv_bfloat162 h01, h23, l01, l23;
    h01.x = __float2bfloat16(v.x); h01.y = __float2bfloat16(v.y);
    h23.x = __float2bfloat16(v.z); h23.y = __float2bfloat16(v.w);
    l01.x = __float2bfloat16(v.x - __bfloat162float(h01.x));
    l01.y = __float2bfloat16(v.y - __bfloat162float(h01.y));
    l23.x = __float2bfloat16(v.z - __bfloat162float(h23.x));
    l23.y = __float2bfloat16(v.w - __bfloat162float(h23.y));
    *(uint2*)(hi + (size_t)r * 128 + lane * 4) =
        make_uint2(*(uint32_t*)&h01, *(uint32_t*)&h23);
    *(uint2*)(lo + (size_t)r * 128 + lane * 4) =
        make_uint2(*(uint32_t*)&l01, *(uint32_t*)&l23);
}

// ---------------- sparse aggregation (gather, warp per node) ----------------
// MODE 0: A only (scaled, dn-folded). MODE 1: dual (A + F). MODE 2: F only.
template <int MODE>
__global__ void agg_kernel(const float* __restrict__ X,
                           const int* __restrict__ rowptr,
                           const int* __restrict__ colidx,
                           const float* __restrict__ srcn,
                           const float* __restrict__ dstn,
                           __nv_bfloat16* __restrict__ Ahi, __nv_bfloat16* __restrict__ Alo,
                           __nv_bfloat16* __restrict__ Fhi, __nv_bfloat16* __restrict__ Flo,
                           int n) {
    int warp = (blockIdx.x * blockDim.x + threadIdx.x) >> 5;
    int lane = threadIdx.x & 31;
    if (warp >= n) return;
    int beg = rowptr[warp];
    int end = rowptr[warp + 1];
    const float4* __restrict__ X4 = (const float4*)X;

    float4 aS = make_float4(0.f, 0.f, 0.f, 0.f);
    float4 aP = make_float4(0.f, 0.f, 0.f, 0.f);
    int e = beg;
    for (; e + 3 < end; e += 4) {
        int s0 = colidx[e], s1 = colidx[e + 1];
        int s2 = colidx[e + 2], s3 = colidx[e + 3];
        float4 v0 = X4[s0 * 32 + lane];
        float4 v1 = X4[s1 * 32 + lane];
        float4 v2 = X4[s2 * 32 + lane];
        float4 v3 = X4[s3 * 32 + lane];
        if (MODE != 2) {
            float n0 = srcn[s0], n1 = srcn[s1], n2 = srcn[s2], n3 = srcn[s3];
            aS.x += v0.x * n0 + v1.x * n1 + v2.x * n2 + v3.x * n3;
            aS.y += v0.y * n0 + v1.y * n1 + v2.y * n2 + v3.y * n3;
            aS.z += v0.z * n0 + v1.z * n1 + v2.z * n2 + v3.z * n3;
            aS.w += v0.w * n0 + v1.w * n1 + v2.w * n2 + v3.w * n3;
        }
        if (MODE != 0) {
            aP.x += v0.x + v1.x + v2.x + v3.x;
            aP.y += v0.y + v1.y + v2.y + v3.y;
            aP.z += v0.z + v1.z + v2.z + v3.z;
            aP.w += v0.w + v1.w + v2.w + v3.w;
        }
    }
    for (; e < end; e++) {
        int s0 = colidx[e];
        float4 v0 = X4[s0 * 32 + lane];
        if (MODE != 2) {
            float n0 = srcn[s0];
            aS.x += v0.x * n0; aS.y += v0.y * n0; aS.z += v0.z * n0; aS.w += v0.w * n0;
        }
        if (MODE != 0) { aP.x += v0.x; aP.y += v0.y; aP.z += v0.z; aP.w += v0.w; }
    }
    if (MODE != 2) {
        float dn = dstn[warp];
        aS.x *= dn; aS.y *= dn; aS.z *= dn; aS.w *= dn;
        split_store(Ahi, Alo, warp, lane, aS);
    }
    if (MODE != 0) split_store(Fhi, Flo, warp, lane, aP);
}

// ---------------- WMMA GEMM, pure cp.async staging --------------------------
#define ALD 136
#define BLD 136
#define SM_AHI 0
#define SM_ALO 17408
#define SM_BHI 34816
#define SM_BLO 69632
#define SM_BIAS 104448
#define SM_TOT 112640

// MODE 0: C = relu(v + bias) (dn already folded into A);  MODE 1: C = v + bias.
template <int MODE, int NSEG>
__global__ void __launch_bounds__(256, 2)
mma_gemm(const __nv_bfloat16* __restrict__ A0h, const __nv_bfloat16* __restrict__ A0l,
         const __nv_bfloat16* __restrict__ A1h, const __nv_bfloat16* __restrict__ A1l,
         const __nv_bfloat16* __restrict__ A2h, const __nv_bfloat16* __restrict__ A2l,
         const __nv_bfloat16* __restrict__ Bh0, const __nv_bfloat16* __restrict__ Bl0,
         const float* __restrict__ bias, float* __restrict__ C, int n) {
    extern __shared__ unsigned char smem[];
    __nv_bfloat16* sAhi = (__nv_bfloat16*)(smem + SM_AHI);
    __nv_bfloat16* sAlo = (__nv_bfloat16*)(smem + SM_ALO);
    __nv_bfloat16* sBhi = (__nv_bfloat16*)(smem + SM_BHI);
    __nv_bfloat16* sBlo = (__nv_bfloat16*)(smem + SM_BLO);
    float*         sBias = (float*)(smem + SM_BIAS);

    const int tid  = threadIdx.x;
    const int wid  = tid >> 5;
    const int row0 = blockIdx.x * 64;

    const __nv_bfloat16* Ahs[3] = {A0h, A1h, A2h};
    const __nv_bfloat16* Als[3] = {A0l, A1l, A2l};

    const int rt = wid >> 1;
    const int ch = wid & 1;
    wmma::fragment<wmma::accumulator, 16, 16, 16, float> acc[4];

#pragma unroll
    for (int seg = 0; seg < NSEG; seg++) {
        if (seg > 0) __syncthreads();   // previous compute done before restage
        // --- A images: 64 rows x 16 chunks x hi/lo ---
        {
            const __nv_bfloat16* Ah = Ahs[seg];
            const __nv_bfloat16* Al = Als[seg];
#pragma unroll
            for (int i = 0; i < 4; i++) {
                int idx = i * 256 + tid;          // 0..1023
                int r   = idx >> 4;
                int c16 = idx & 15;
                size_t g = (size_t)(row0 + r) * 128 + c16 * 8;
                __pipeline_memcpy_async(sAhi + r * ALD + c16 * 8, Ah + g, 16);
                __pipeline_memcpy_async(sAlo + r * ALD + c16 * 8, Al + g, 16);
            }
        }
        // --- B images: 128 rows x 16 chunks x hi/lo ---
        {
            const __nv_bfloat16* Bh = Bh0 + seg * DD * DD;
            const __nv_bfloat16* Bl = Bl0 + seg * DD * DD;
#pragma unroll
            for (int i = 0; i < 8; i++) {
                int idx = i * 256 + tid;          // 0..2047
                int r   = idx >> 4;
                int c16 = idx & 15;
                __pipeline_memcpy_async(sBhi + r * BLD + c16 * 8, Bh + r * 128 + c16 * 8, 16);
                __pipeline_memcpy_async(sBlo + r * BLD + c16 * 8, Bl + r * 128 + c16 * 8, 16);
            }
        }
        __pipeline_commit();
        if (seg == 0) {
            for (int idx = tid; idx < 2048; idx += 256)
                sBias[idx] = bias[(idx >> 8) * 16 + (idx & 15)];
        }
        __pipeline_wait_prior(0);
        __syncthreads();

        if (seg == 0) {
#pragma unroll
            for (int j = 0; j < 4; j++)
                wmma::load_matrix_sync(acc[j], sBias + (ch * 4 + j) * 256, 16,
                                       wmma::mem_row_major);
        }

#pragma unroll
        for (int kk = 0; kk < 8; kk++) {
            wmma::fragment<wmma::matrix_a, 16, 16, 16, __nv_bfloat16, wmma::row_major> ah, al;
            wmma::load_matrix_sync(ah, sAhi + (rt * 16) * ALD + kk * 16, ALD);
            wmma::load_matrix_sync(al, sAlo + (rt * 16) * ALD + kk * 16, ALD);
#pragma unroll
            for (int j = 0; j < 4; j++) {
                int nt = ch * 4 + j;
                wmma::fragment<wmma::matrix_b, 16, 16, 16, __nv_bfloat16, wmma::row_major> bh, bl;
                wmma::load_matrix_sync(bh, sBhi + (kk * 16) * BLD + nt * 16, BLD);
                wmma::load_matrix_sync(bl, sBlo + (kk * 16) * BLD + nt * 16, BLD);
                wmma::mma_sync(acc[j], ah, bh, acc[j]);
                wmma::mma_sync(acc[j], ah, bl, acc[j]);
                wmma::mma_sync(acc[j], al, bh, acc[j]);
            }
        }
    }

    if (row0 + rt * 16 + 16 <= n) {
#pragma unroll
        for (int j = 0; j < 4; j++) {
            if (MODE == 0) {
#pragma unroll
                for (int i = 0; i < acc[j].num_elements; i++)
                    acc[j].x[i] = fmaxf(acc[j].x[i], 0.f);
            }
            wmma::store_matrix_sync(C + (size_t)(row0 + rt * 16) * 128 + (ch * 4 + j) * 16,
                                    acc[j], 128, wmma::mem_row_major);
        }
    }
}

// ---------------------------------------------------------------------------
extern "C" void kernel_launch(void* const* d_in, const int* in_sizes, int n_in,
                              void* d_out, int out_size) {
    const float* feats = (const float*)d_in[0];
    const int*   src   = (const int*)  d_in[1];
    const int*   dst   = (const int*)  d_in[2];
    const float* W0    = (const float*)d_in[3];
    const float* b0    = (const float*)d_in[4];
    const float* W1    = (const float*)d_in[5];
    const float* b1    = (const float*)d_in[6];
    const float* W2    = (const float*)d_in[7];
    const float* b2    = (const float*)d_in[8];
    const float* Wout  = (const float*)d_in[9];
    const float* bout  = (const float*)d_in[10];
    float*       out   = (float*)d_out;

    const int n = in_sizes[0] / DD;
    const int e = in_sizes[1];

    float *h0, *h1, *h2, *srcn, *dstn;
    int *outdeg, *indeg, *rowptr, *cursor, *colidx, *bsum;
    __nv_bfloat16 *Ahi, *Alo, *Fhi, *Flo, *Bhi, *Blo;
    cudaGetSymbolAddress((void**)&h0,     g_h0);
    cudaGetSymbolAddress((void**)&h1,     g_h1);
    cudaGetSymbolAddress((void**)&h2,     g_h2);
    cudaGetSymbolAddress((void**)&Ahi,    g_Ahi);
    cudaGetSymbolAddress((void**)&Alo,    g_Alo);
    cudaGetSymbolAddress((void**)&Fhi,    g_Fhi);
    cudaGetSymbolAddress((void**)&Flo,    g_Flo);
    cudaGetSymbolAddress((void**)&srcn,   g_srcn);
    cudaGetSymbolAddress((void**)&dstn,   g_dstn);
    cudaGetSymbolAddress((void**)&outdeg, g_outdeg);
    cudaGetSymbolAddress((void**)&indeg,  g_indeg);
    cudaGetSymbolAddress((void**)&rowptr, g_rowptr);
    cudaGetSymbolAddress((void**)&cursor, g_cursor);
    cudaGetSymbolAddress((void**)&colidx, g_colidx);
    cudaGetSymbolAddress((void**)&bsum,   g_bsum);
    cudaGetSymbolAddress((void**)&Bhi,    g_Bhi);
    cudaGetSymbolAddress((void**)&Blo,    g_Blo);

    const int nbN  = (n + 255) / 256;
    const int nbE  = (e + 255) / 256;
    const int nbAg = (n + 7) / 8;
    const int nbT  = (n + 63) / 64;

    cudaFuncSetAttribute(mma_gemm<0, 1>, cudaFuncAttributeMaxDynamicSharedMemorySize, SM_TOT);
    cudaFuncSetAttribute(mma_gemm<1, 3>, cudaFuncAttributeMaxDynamicSharedMemorySize, SM_TOT);

    // ---- CSR build + norms + weight conversion ----
    zero_ints      <<<nbN, 256>>>(outdeg, indeg, n);
    conv_w         <<<(6 * DD * DD + 255) / 256, 256>>>(W0, W1, W2, Wout, Bhi, Blo);
    deg_hist       <<<nbE, 256>>>(src, dst, outdeg, indeg, e);
    scan_block_sums<<<nbN, 256>>>(indeg, bsum, n);
    scan_bsums     <<<1,   256>>>(bsum, nbN);
    scan_final     <<<nbN, 256>>>(indeg, bsum, outdeg, rowptr, cursor, srcn, dstn, n, e);
    scatter_edges  <<<nbE, 256>>>(src, dst, cursor, colidx, e);

    // ---- layer 1 ----
    agg_kernel<0><<<nbAg, 256>>>(feats, rowptr, colidx, srcn, dstn,
                                 Ahi, Alo, nullptr, nullptr, n);
    mma_gemm<0, 1><<<nbT, 256, SM_TOT>>>(Ahi, Alo, nullptr, nullptr, nullptr, nullptr,
                                         Bhi + 0 * DD * DD, Blo + 0 * DD * DD,
                                         b0, h0, n);
    // ---- layer 2 (+ F0) ----
    agg_kernel<1><<<nbAg, 256>>>(h0, rowptr, colidx, srcn, dstn,
                                 Ahi, Alo, Fhi + 0 * NPAD * DD, Flo + 0 * NPAD * DD, n);
    mma_gemm<0, 1><<<nbT, 256, SM_TOT>>>(Ahi, Alo, nullptr, nullptr, nullptr, nullptr,
                                         Bhi + 1 * DD * DD, Blo + 1 * DD * DD,
                                         b1, h1, n);
    // ---- layer 3 (+ F1) ----
    agg_kernel<1><<<nbAg, 256>>>(h1, rowptr, colidx, srcn, dstn,
                                 Ahi, Alo, Fhi + 1 * NPAD * DD, Flo + 1 * NPAD * DD, n);
    mma_gemm<0, 1><<<nbT, 256, SM_TOT>>>(Ahi, Alo, nullptr, nullptr, nullptr, nullptr,
                                         Bhi + 2 * DD * DD, Blo + 2 * DD * DD,
                                         b2, h2, n);
    // ---- F2 = plain agg(h2) ----
    agg_kernel<2><<<nbAg, 256>>>(h2, rowptr, colidx, srcn, dstn,
                                 nullptr, nullptr,
                                 Fhi + 2 * NPAD * DD, Flo + 2 * NPAD * DD, n);
    // ---- out = [F0 F1 F2] @ Wout + bout ----
    mma_gemm<1, 3><<<nbT, 256, SM_TOT>>>(Fhi + 0 * NPAD * DD, Flo + 0 * NPAD * DD,
                                         Fhi + 1 * NPAD * DD, Flo + 1 * NPAD * DD,
                                         Fhi + 2 * NPAD * DD, Flo + 2 * NPAD * DD,
                                         Bhi + 3 * DD * DD, Blo + 3 * DD * DD,
                                         bout, out, n);
}

// round 11
// speedup vs baseline: 1.2864x; 1.0113x over previous
#include <cuda_runtime.h>
#include <cuda_bf16.h>
#include <cuda_fp16.h>
#include <mma.h>
#include <cuda_pipeline.h>
#include <cstdint>

using namespace nvcuda;

// ---------------------------------------------------------------------------
// JKNet R11 (= R10 resubmit after infra flake): fp16 hidden states (halves
// gather traffic, the dominant cost) + packed (colidx,srcn) int2 edge records.
// Gather accumulates fp32; GEMM operands remain bf16 hi/lo of fp32 sums.
// ---------------------------------------------------------------------------

#define NN 50000
#define EE 800000
#define DD 128
#define NPAD (NN + 64)

// ---------------- scratch ---------------------------------------------------
__device__ __half g_h0[NN * DD];
__device__ __half g_h1[NN * DD];
__device__ __half g_h2[NN * DD];
__device__ __nv_bfloat16 g_Ahi[NPAD * DD];
__device__ __nv_bfloat16 g_Alo[NPAD * DD];
__device__ __nv_bfloat16 g_Fhi[3][NPAD * DD];
__device__ __nv_bfloat16 g_Flo[3][NPAD * DD];
__device__ float g_srcn[NN];
__device__ float g_dstn[NN];
__device__ int   g_outdeg[NN];
__device__ int   g_indeg [NN];
__device__ int   g_rowptr[NN + 1];
__device__ int   g_cursor[NN];
__device__ int2  g_edge[EE];            // (src, srcn bits)
__device__ int   g_bsum[256];
__device__ __nv_bfloat16 g_Bhi[6 * DD * DD];
__device__ __nv_bfloat16 g_Blo[6 * DD * DD];

// ---------------- CSR build -------------------------------------------------
__global__ void zero_ints(int* __restrict__ a, int* __restrict__ b, int n) {
    int i = blockIdx.x * blockDim.x + threadIdx.x;
    if (i < n) { a[i] = 0; b[i] = 0; }
}
__global__ void deg_hist(const int* __restrict__ src, const int* __restrict__ dst,
                         int* __restrict__ outdeg, int* __restrict__ indeg, int e) {
    int i = blockIdx.x * blockDim.x + threadIdx.x;
    if (i < e) { atomicAdd(&outdeg[src[i]], 1); atomicAdd(&indeg[dst[i]], 1); }
}
__global__ void scan_block_sums(const int* __restrict__ deg, int* __restrict__ bsum, int n) {
    __shared__ int s[256];
    int i = blockIdx.x * 256 + threadIdx.x;
    s[threadIdx.x] = (i < n) ? deg[i] : 0;
    __syncthreads();
    for (int off = 128; off > 0; off >>= 1) {
        if (threadIdx.x < off) s[threadIdx.x] += s[threadIdx.x + off];
        __syncthreads();
    }
    if (threadIdx.x == 0) bsum[blockIdx.x] = s[0];
}
__global__ void scan_bsums(int* __restrict__ bsum, int nb) {
    __shared__ int s[256];
    int t = threadIdx.x;
    int v = (t < nb) ? bsum[t] : 0;
    s[t] = v;
    __syncthreads();
    for (int off = 1; off < 256; off <<= 1) {
        int add = (t >= off) ? s[t - off] : 0;
        __syncthreads();
        s[t] += add;
        __syncthreads();
    }
    if (t < nb) bsum[t] = s[t] - v;
}
__global__ void scan_final(const int* __restrict__ deg, const int* __restrict__ bsum,
                           const int* __restrict__ outdeg,
                           int* __restrict__ rowptr, int* __restrict__ cursor,
                           float* __restrict__ sn, float* __restrict__ dn,
                           int n, int etot) {
    __shared__ int s[256];
    int t = threadIdx.x;
    int i = blockIdx.x * 256 + t;
    int v = (i < n) ? deg[i] : 0;
    s[t] = v;
    __syncthreads();
    for (int off = 1; off < 256; off <<= 1) {
        int add = (t >= off) ? s[t - off] : 0;
        __syncthreads();
        s[t] += add;
        __syncthreads();
    }
    int ex = bsum[blockIdx.x] + s[t] - v;
    if (i < n) {
        rowptr[i] = ex;
        cursor[i] = ex;
        sn[i] = rsqrtf((float)max(outdeg[i], 1));
        dn[i] = rsqrtf((float)max(v, 1));
    }
    if (i == 0) rowptr[n] = etot;
}
__global__ void scatter_edges(const int* __restrict__ src, const int* __restrict__ dst,
                              const float* __restrict__ srcn,
                              int* __restrict__ cursor, int2* __restrict__ edge, int e) {
    int i = blockIdx.x * blockDim.x + threadIdx.x;
    if (i < e) {
        int s = src[i];
        int p = atomicAdd(&cursor[dst[i]], 1);
        edge[p] = make_int2(s, __float_as_int(srcn[s]));
    }
}

// ---------------- W conversion ----------------------------------------------
__global__ void conv_w(const float* __restrict__ W0, const float* __restrict__ W1,
                       const float* __restrict__ W2, const float* __restrict__ Wout,
                       __nv_bfloat16* __restrict__ hi, __nv_bfloat16* __restrict__ lo) {
    int idx = blockIdx.x * blockDim.x + threadIdx.x;
    if (idx >= 6 * DD * DD) return;
    int m = idx / (DD * DD);
    int rem = idx % (DD * DD);
    const float* src = (m == 0) ? W0 : (m == 1) ? W1 : (m == 2) ? W2
                                     : (Wout + (m - 3) * DD * DD);
    float v = src[rem];
    __nv_bfloat16 h = __float2bfloat16(v);
    __nv_bfloat16 l = __float2bfloat16(v - __bfloat162float(h));
    hi[idx] = h;
    lo[idx] = l;
}

// split a float4 (cols lane*4..+3 of row r) into bf16 hi/lo images
__device__ __forceinline__ void split_store(__nv_bfloat16* __restrict__ hi,
                                            __nv_bfloat16* __restrict__ lo,
                                            int r, int lane, float4 v) {
    __nv_bfloat162 h01, h23, l01, l23;
    h01.x = __float2bfloat16(v.x); h01.y = __float2bfloat16(v.y);
    h23.x = __float2bfloat16(v.z); h23.y = __float2bfloat16(v.w);
    l01.x = __float2bfloat16(v.x - __bfloat162float(h01.x));
    l01.y = __float2bfloat16(v.y - __bfloat162float(h01.y));
    l23.x = __float2bfloat16(v.z - __bfloat162float(h23.x));
    l23.y = __float2bfloat16(v.w - __bfloat162float(h23.y));
    *(uint2*)(hi + (size_t)r * 128 + lane * 4) =
        make_uint2(*(uint32_t*)&h01, *(uint32_t*)&h23);
    *(uint2*)(lo + (size_t)r * 128 + lane * 4) =
        make_uint2(*(uint32_t*)&l01, *(uint32_t*)&l23);
}

// row loaders (4 elements at cols lane*4..+3)
__device__ __forceinline__ float4 load_row4(const float* __restrict__ X, int s, int lane) {
    return ((const float4*)X)[s * 32 + lane];
}
__device__ __forceinline__ float4 load_row4(const __half* __restrict__ X, int s, int lane) {
    uint2 u = *(const uint2*)(X + (size_t)s * 128 + lane * 4);
    float2 f0 = __half22float2(*(__half2*)&u.x);
    float2 f1 = __half22float2(*(__half2*)&u.y);
    return make_float4(f0.x, f0.y, f1.x, f1.y);
}

// ---------------- sparse aggregation (gather, warp per node) ----------------
// MODE 0: A only (scaled, dn-folded). MODE 1: dual (A + F). MODE 2: F only.
template <int MODE, typename TIN>
__global__ void agg_kernel(const TIN* __restrict__ X,
                           const int* __restrict__ rowptr,
                           const int2* __restrict__ edge,
                           const float* __restrict__ dstn,
                           __nv_bfloat16* __restrict__ Ahi, __nv_bfloat16* __restrict__ Alo,
                           __nv_bfloat16* __restrict__ Fhi, __nv_bfloat16* __restrict__ Flo,
                           int n) {
    int warp = (blockIdx.x * blockDim.x + threadIdx.x) >> 5;
    int lane = threadIdx.x & 31;
    if (warp >= n) return;
    int beg = rowptr[warp];
    int end = rowptr[warp + 1];

    float4 aS = make_float4(0.f, 0.f, 0.f, 0.f);
    float4 aP = make_float4(0.f, 0.f, 0.f, 0.f);
    int e = beg;
    for (; e + 3 < end; e += 4) {
        int2 e0 = edge[e],     e1 = edge[e + 1];
        int2 e2 = edge[e + 2], e3 = edge[e + 3];
        float4 v0 = load_row4(X, e0.x, lane);
        float4 v1 = load_row4(X, e1.x, lane);
        float4 v2 = load_row4(X, e2.x, lane);
        float4 v3 = load_row4(X, e3.x, lane);
        if (MODE != 2) {
            float n0 = __int_as_float(e0.y), n1 = __int_as_float(e1.y);
            float n2 = __int_as_float(e2.y), n3 = __int_as_float(e3.y);
            aS.x += v0.x * n0 + v1.x * n1 + v2.x * n2 + v3.x * n3;
            aS.y += v0.y * n0 + v1.y * n1 + v2.y * n2 + v3.y * n3;
            aS.z += v0.z * n0 + v1.z * n1 + v2.z * n2 + v3.z * n3;
            aS.w += v0.w * n0 + v1.w * n1 + v2.w * n2 + v3.w * n3;
        }
        if (MODE != 0) {
            aP.x += v0.x + v1.x + v2.x + v3.x;
            aP.y += v0.y + v1.y + v2.y + v3.y;
            aP.z += v0.z + v1.z + v2.z + v3.z;
            aP.w += v0.w + v1.w + v2.w + v3.w;
        }
    }
    for (; e < end; e++) {
        int2 e0 = edge[e];
        float4 v0 = load_row4(X, e0.x, lane);
        if (MODE != 2) {
            float n0 = __int_as_float(e0.y);
            aS.x += v0.x * n0; aS.y += v0.y * n0; aS.z += v0.z * n0; aS.w += v0.w * n0;
        }
        if (MODE != 0) { aP.x += v0.x; aP.y += v0.y; aP.z += v0.z; aP.w += v0.w; }
    }
    if (MODE != 2) {
        float dn = dstn[warp];
        aS.x *= dn; aS.y *= dn; aS.z *= dn; aS.w *= dn;
        split_store(Ahi, Alo, warp, lane, aS);
    }
    if (MODE != 0) split_store(Fhi, Flo, warp, lane, aP);
}

// ---------------- WMMA GEMM, pure cp.async staging --------------------------
#define ALD 136
#define BLD 136
#define SM_AHI 0
#define SM_ALO 17408
#define SM_BHI 34816
#define SM_BLO 69632
#define SM_BIAS 104448
#define SM_TOT 112640

// MODE 0: H(fp16) = relu(v + bias) (dn folded into A);  MODE 1: C(fp32) = v + bias.
template <int MODE, int NSEG>
__global__ void __launch_bounds__(256, 2)
mma_gemm(const __nv_bfloat16* __restrict__ A0h, const __nv_bfloat16* __restrict__ A0l,
         const __nv_bfloat16* __restrict__ A1h, const __nv_bfloat16* __restrict__ A1l,
         const __nv_bfloat16* __restrict__ A2h, const __nv_bfloat16* __restrict__ A2l,
         const __nv_bfloat16* __restrict__ Bh0, const __nv_bfloat16* __restrict__ Bl0,
         const float* __restrict__ bias,
         __half* __restrict__ Hout, float* __restrict__ Cout, int n) {
    extern __shared__ unsigned char smem[];
    __nv_bfloat16* sAhi = (__nv_bfloat16*)(smem + SM_AHI);
    __nv_bfloat16* sAlo = (__nv_bfloat16*)(smem + SM_ALO);
    __nv_bfloat16* sBhi = (__nv_bfloat16*)(smem + SM_BHI);
    __nv_bfloat16* sBlo = (__nv_bfloat16*)(smem + SM_BLO);
    float*         sBias = (float*)(smem + SM_BIAS);

    const int tid  = threadIdx.x;
    const int wid  = tid >> 5;
    const int row0 = blockIdx.x * 64;

    const __nv_bfloat16* Ahs[3] = {A0h, A1h, A2h};
    const __nv_bfloat16* Als[3] = {A0l, A1l, A2l};

    const int rt = wid >> 1;
    const int ch = wid & 1;
    wmma::fragment<wmma::accumulator, 16, 16, 16, float> acc[4];

#pragma unroll
    for (int seg = 0; seg < NSEG; seg++) {
        if (seg > 0) __syncthreads();
        {
            const __nv_bfloat16* Ah = Ahs[seg];
            const __nv_bfloat16* Al = Als[seg];
#pragma unroll
            for (int i = 0; i < 4; i++) {
                int idx = i * 256 + tid;
                int r   = idx >> 4;
                int c16 = idx & 15;
                size_t g = (size_t)(row0 + r) * 128 + c16 * 8;
                __pipeline_memcpy_async(sAhi + r * ALD + c16 * 8, Ah + g, 16);
                __pipeline_memcpy_async(sAlo + r * ALD + c16 * 8, Al + g, 16);
            }
        }
        {
            const __nv_bfloat16* Bh = Bh0 + seg * DD * DD;
            const __nv_bfloat16* Bl = Bl0 + seg * DD * DD;
#pragma unroll
            for (int i = 0; i < 8; i++) {
                int idx = i * 256 + tid;
                int r   = idx >> 4;
                int c16 = idx & 15;
                __pipeline_memcpy_async(sBhi + r * BLD + c16 * 8, Bh + r * 128 + c16 * 8, 16);
                __pipeline_memcpy_async(sBlo + r * BLD + c16 * 8, Bl + r * 128 + c16 * 8, 16);
            }
        }
        __pipeline_commit();
        if (seg == 0) {
            for (int idx = tid; idx < 2048; idx += 256)
                sBias[idx] = bias[(idx >> 8) * 16 + (idx & 15)];
        }
        __pipeline_wait_prior(0);
        __syncthreads();

        if (seg == 0) {
#pragma unroll
            for (int j = 0; j < 4; j++)
                wmma::load_matrix_sync(acc[j], sBias + (ch * 4 + j) * 256, 16,
                                       wmma::mem_row_major);
        }

#pragma unroll
        for (int kk = 0; kk < 8; kk++) {
            wmma::fragment<wmma::matrix_a, 16, 16, 16, __nv_bfloat16, wmma::row_major> ah, al;
            wmma::load_matrix_sync(ah, sAhi + (rt * 16) * ALD + kk * 16, ALD);
            wmma::load_matrix_sync(al, sAlo + (rt * 16) * ALD + kk * 16, ALD);
#pragma unroll
            for (int j = 0; j < 4; j++) {
                int nt = ch * 4 + j;
                wmma::fragment<wmma::matrix_b, 16, 16, 16, __nv_bfloat16, wmma::row_major> bh, bl;
                wmma::load_matrix_sync(bh, sBhi + (kk * 16) * BLD + nt * 16, BLD);
                wmma::load_matrix_sync(bl, sBlo + (kk * 16) * BLD + nt * 16, BLD);
                wmma::mma_sync(acc[j], ah, bh, acc[j]);
                wmma::mma_sync(acc[j], ah, bl, acc[j]);
                wmma::mma_sync(acc[j], al, bh, acc[j]);
            }
        }
    }

    if (MODE == 1) {
        // fp32 direct store
        if (row0 + rt * 16 + 16 <= n) {
#pragma unroll
            for (int j = 0; j < 4; j++)
                wmma::store_matrix_sync(Cout + (size_t)(row0 + rt * 16) * 128 + (ch * 4 + j) * 16,
                                        acc[j], 128, wmma::mem_row_major);
        }
    } else {
        // relu on fragments -> smem fp32 -> fp16 global (fragment layout opaque)
        __syncthreads();   // done reading sA before overwriting with result tile
        float* smemF = (float*)(smem + SM_AHI);   // 64*128*4 = 32KB
        if (row0 + rt * 16 + 16 <= n) {
#pragma unroll
            for (int j = 0; j < 4; j++) {
#pragma unroll
                for (int i = 0; i < acc[j].num_elements; i++)
                    acc[j].x[i] = fmaxf(acc[j].x[i], 0.f);
                wmma::store_matrix_sync(smemF + (rt * 16) * 128 + (ch * 4 + j) * 16,
                                        acc[j], 128, wmma::mem_row_major);
            }
        }
        __syncthreads();
#pragma unroll
        for (int i = 0; i < 8; i++) {
            int idx4 = i * 256 + tid;   // 0..2047 float4
            int r    = idx4 >> 5;
            int c4   = idx4 & 31;
            if (row0 + r < n) {
                float4 v = ((const float4*)smemF)[idx4];
                __half2 p0 = __floats2half2_rn(v.x, v.y);
                __half2 p1 = __floats2half2_rn(v.z, v.w);
                *(uint2*)(Hout + (size_t)(row0 + r) * 128 + c4 * 4) =
                    make_uint2(*(uint32_t*)&p0, *(uint32_t*)&p1);
            }
        }
    }
}

// ---------------------------------------------------------------------------
extern "C" void kernel_launch(void* const* d_in, const int* in_sizes, int n_in,
                              void* d_out, int out_size) {
    const float* feats = (const float*)d_in[0];
    const int*   src   = (const int*)  d_in[1];
    const int*   dst   = (const int*)  d_in[2];
    const float* W0    = (const float*)d_in[3];
    const float* b0    = (const float*)d_in[4];
    const float* W1    = (const float*)d_in[5];
    const float* b1    = (const float*)d_in[6];
    const float* W2    = (const float*)d_in[7];
    const float* b2    = (const float*)d_in[8];
    const float* Wout  = (const float*)d_in[9];
    const float* bout  = (const float*)d_in[10];
    float*       out   = (float*)d_out;

    const int n = in_sizes[0] / DD;
    const int e = in_sizes[1];

    __half *h0, *h1, *h2;
    float *srcn, *dstn;
    int *outdeg, *indeg, *rowptr, *cursor, *bsum;
    int2 *edge;
    __nv_bfloat16 *Ahi, *Alo, *Fhi, *Flo, *Bhi, *Blo;
    cudaGetSymbolAddress((void**)&h0,     g_h0);
    cudaGetSymbolAddress((void**)&h1,     g_h1);
    cudaGetSymbolAddress((void**)&h2,     g_h2);
    cudaGetSymbolAddress((void**)&Ahi,    g_Ahi);
    cudaGetSymbolAddress((void**)&Alo,    g_Alo);
    cudaGetSymbolAddress((void**)&Fhi,    g_Fhi);
    cudaGetSymbolAddress((void**)&Flo,    g_Flo);
    cudaGetSymbolAddress((void**)&srcn,   g_srcn);
    cudaGetSymbolAddress((void**)&dstn,   g_dstn);
    cudaGetSymbolAddress((void**)&outdeg, g_outdeg);
    cudaGetSymbolAddress((void**)&indeg,  g_indeg);
    cudaGetSymbolAddress((void**)&rowptr, g_rowptr);
    cudaGetSymbolAddress((void**)&cursor, g_cursor);
    cudaGetSymbolAddress((void**)&edge,   g_edge);
    cudaGetSymbolAddress((void**)&bsum,   g_bsum);
    cudaGetSymbolAddress((void**)&Bhi,    g_Bhi);
    cudaGetSymbolAddress((void**)&Blo,    g_Blo);

    const int nbN  = (n + 255) / 256;
    const int nbE  = (e + 255) / 256;
    const int nbAg = (n + 7) / 8;
    const int nbT  = (n + 63) / 64;

    cudaFuncSetAttribute(mma_gemm<0, 1>, cudaFuncAttributeMaxDynamicSharedMemorySize, SM_TOT);
    cudaFuncSetAttribute(mma_gemm<1, 3>, cudaFuncAttributeMaxDynamicSharedMemorySize, SM_TOT);

    // ---- CSR build + norms + weight conversion ----
    zero_ints      <<<nbN, 256>>>(outdeg, indeg, n);
    conv_w         <<<(6 * DD * DD + 255) / 256, 256>>>(W0, W1, W2, Wout, Bhi, Blo);
    deg_hist       <<<nbE, 256>>>(src, dst, outdeg, indeg, e);
    scan_block_sums<<<nbN, 256>>>(indeg, bsum, n);
    scan_bsums     <<<1,   256>>>(bsum, nbN);
    scan_final     <<<nbN, 256>>>(indeg, bsum, outdeg, rowptr, cursor, srcn, dstn, n, e);
    scatter_edges  <<<nbE, 256>>>(src, dst, srcn, cursor, edge, e);

    // ---- layer 1 (feats fp32) ----
    agg_kernel<0, float><<<nbAg, 256>>>(feats, rowptr, edge, dstn,
                                        Ahi, Alo, nullptr, nullptr, n);
    mma_gemm<0, 1><<<nbT, 256, SM_TOT>>>(Ahi, Alo, nullptr, nullptr, nullptr, nullptr,
                                         Bhi + 0 * DD * DD, Blo + 0 * DD * DD,
                                         b0, h0, nullptr, n);
    // ---- layer 2 (+ F0), h0 fp16 ----
    agg_kernel<1, __half><<<nbAg, 256>>>(h0, rowptr, edge, dstn,
                                         Ahi, Alo, Fhi + 0 * NPAD * DD, Flo + 0 * NPAD * DD, n);
    mma_gemm<0, 1><<<nbT, 256, SM_TOT>>>(Ahi, Alo, nullptr, nullptr, nullptr, nullptr,
                                         Bhi + 1 * DD * DD, Blo + 1 * DD * DD,
                                         b1, h1, nullptr, n);
    // ---- layer 3 (+ F1), h1 fp16 ----
    agg_kernel<1, __half><<<nbAg, 256>>>(h1, rowptr, edge, dstn,
                                         Ahi, Alo, Fhi + 1 * NPAD * DD, Flo + 1 * NPAD * DD, n);
    mma_gemm<0, 1><<<nbT, 256, SM_TOT>>>(Ahi, Alo, nullptr, nullptr, nullptr, nullptr,
                                         Bhi + 2 * DD * DD, Blo + 2 * DD * DD,
                                         b2, h2, nullptr, n);
    // ---- F2 = plain agg(h2) ----
    agg_kernel<2, __half><<<nbAg, 256>>>(h2, rowptr, edge, dstn,
                                         nullptr, nullptr,
                                         Fhi + 2 * NPAD * DD, Flo + 2 * NPAD * DD, n);
    // ---- out = [F0 F1 F2] @ Wout + bout ----
    mma_gemm<1, 3><<<nbT, 256, SM_TOT>>>(Fhi + 0 * NPAD * DD, Flo + 0 * NPAD * DD,
                                         Fhi + 1 * NPAD * DD, Flo + 1 * NPAD * DD,
                                         Fhi + 2 * NPAD * DD, Flo + 2 * NPAD * DD,
                                         Bhi + 3 * DD * DD, Blo + 3 * DD * DD,
                                         bout, nullptr, out, n);
}

// round 13
// speedup vs baseline: 1.3235x; 1.0288x over previous
#include <cuda_runtime.h>
#include <cuda_bf16.h>
#include <cuda_fp16.h>
#include <mma.h>
#include <cuda_pipeline.h>
#include <cstdint>

using namespace nvcuda;

// ---------------------------------------------------------------------------
// JKNet R13 (= R12 resubmit after infra flake; R10->R11 precedent):
// half-warp-per-node fp16 gather (2x independent edge chains per warp,
// 16B/lane loads) on top of R11's fp16-hidden-state + packed-edge design.
// ---------------------------------------------------------------------------

#define NN 50000
#define EE 800000
#define DD 128
#define NPAD (NN + 64)

// ---------------- scratch ---------------------------------------------------
__device__ __half g_h0[NN * DD];
__device__ __half g_h1[NN * DD];
__device__ __half g_h2[NN * DD];
__device__ __nv_bfloat16 g_Ahi[NPAD * DD];
__device__ __nv_bfloat16 g_Alo[NPAD * DD];
__device__ __nv_bfloat16 g_Fhi[3][NPAD * DD];
__device__ __nv_bfloat16 g_Flo[3][NPAD * DD];
__device__ float g_srcn[NN];
__device__ float g_dstn[NN];
__device__ int   g_outdeg[NN];
__device__ int   g_indeg [NN];
__device__ int   g_rowptr[NN + 1];
__device__ int   g_cursor[NN];
__device__ int2  g_edge[EE];            // (src, srcn bits)
__device__ int   g_bsum[256];
__device__ __nv_bfloat16 g_Bhi[6 * DD * DD];
__device__ __nv_bfloat16 g_Blo[6 * DD * DD];

// ---------------- CSR build -------------------------------------------------
__global__ void zero_ints(int* __restrict__ a, int* __restrict__ b, int n) {
    int i = blockIdx.x * blockDim.x + threadIdx.x;
    if (i < n) { a[i] = 0; b[i] = 0; }
}
__global__ void deg_hist(const int* __restrict__ src, const int* __restrict__ dst,
                         int* __restrict__ outdeg, int* __restrict__ indeg, int e) {
    int i = blockIdx.x * blockDim.x + threadIdx.x;
    if (i < e) { atomicAdd(&outdeg[src[i]], 1); atomicAdd(&indeg[dst[i]], 1); }
}
__global__ void scan_block_sums(const int* __restrict__ deg, int* __restrict__ bsum, int n) {
    __shared__ int s[256];
    int i = blockIdx.x * 256 + threadIdx.x;
    s[threadIdx.x] = (i < n) ? deg[i] : 0;
    __syncthreads();
    for (int off = 128; off > 0; off >>= 1) {
        if (threadIdx.x < off) s[threadIdx.x] += s[threadIdx.x + off];
        __syncthreads();
    }
    if (threadIdx.x == 0) bsum[blockIdx.x] = s[0];
}
__global__ void scan_bsums(int* __restrict__ bsum, int nb) {
    __shared__ int s[256];
    int t = threadIdx.x;
    int v = (t < nb) ? bsum[t] : 0;
    s[t] = v;
    __syncthreads();
    for (int off = 1; off < 256; off <<= 1) {
        int add = (t >= off) ? s[t - off] : 0;
        __syncthreads();
        s[t] += add;
        __syncthreads();
    }
    if (t < nb) bsum[t] = s[t] - v;
}
__global__ void scan_final(const int* __restrict__ deg, const int* __restrict__ bsum,
                           const int* __restrict__ outdeg,
                           int* __restrict__ rowptr, int* __restrict__ cursor,
                           float* __restrict__ sn, float* __restrict__ dn,
                           int n, int etot) {
    __shared__ int s[256];
    int t = threadIdx.x;
    int i = blockIdx.x * 256 + t;
    int v = (i < n) ? deg[i] : 0;
    s[t] = v;
    __syncthreads();
    for (int off = 1; off < 256; off <<= 1) {
        int add = (t >= off) ? s[t - off] : 0;
        __syncthreads();
        s[t] += add;
        __syncthreads();
    }
    int ex = bsum[blockIdx.x] + s[t] - v;
    if (i < n) {
        rowptr[i] = ex;
        cursor[i] = ex;
        sn[i] = rsqrtf((float)max(outdeg[i], 1));
        dn[i] = rsqrtf((float)max(v, 1));
    }
    if (i == 0) rowptr[n] = etot;
}
__global__ void scatter_edges(const int* __restrict__ src, const int* __restrict__ dst,
                              const float* __restrict__ srcn,
                              int* __restrict__ cursor, int2* __restrict__ edge, int e) {
    int i = blockIdx.x * blockDim.x + threadIdx.x;
    if (i < e) {
        int s = src[i];
        int p = atomicAdd(&cursor[dst[i]], 1);
        edge[p] = make_int2(s, __float_as_int(srcn[s]));
    }
}

// ---------------- W conversion ----------------------------------------------
__global__ void conv_w(const float* __restrict__ W0, const float* __restrict__ W1,
                       const float* __restrict__ W2, const float* __restrict__ Wout,
                       __nv_bfloat16* __restrict__ hi, __nv_bfloat16* __restrict__ lo) {
    int idx = blockIdx.x * blockDim.x + threadIdx.x;
    if (idx >= 6 * DD * DD) return;
    int m = idx / (DD * DD);
    int rem = idx % (DD * DD);
    const float* src = (m == 0) ? W0 : (m == 1) ? W1 : (m == 2) ? W2
                                     : (Wout + (m - 3) * DD * DD);
    float v = src[rem];
    __nv_bfloat16 h = __float2bfloat16(v);
    __nv_bfloat16 l = __float2bfloat16(v - __bfloat162float(h));
    hi[idx] = h;
    lo[idx] = l;
}

// split a float4 (cols lane*4..+3 of row r) into bf16 hi/lo images
__device__ __forceinline__ void split_store(__nv_bfloat16* __restrict__ hi,
                                            __nv_bfloat16* __restrict__ lo,
                                            int r, int lane, float4 v) {
    __nv_bfloat162 h01, h23, l01, l23;
    h01.x = __float2bfloat16(v.x); h01.y = __float2bfloat16(v.y);
    h23.x = __float2bfloat16(v.z); h23.y = __float2bfloat16(v.w);
    l01.x = __float2bfloat16(v.x - __bfloat162float(h01.x));
    l01.y = __float2bfloat16(v.y - __bfloat162float(h01.y));
    l23.x = __float2bfloat16(v.z - __bfloat162float(h23.x));
    l23.y = __float2bfloat16(v.w - __bfloat162float(h23.y));
    *(uint2*)(hi + (size_t)r * 128 + lane * 4) =
        make_uint2(*(uint32_t*)&h01, *(uint32_t*)&h23);
    *(uint2*)(lo + (size_t)r * 128 + lane * 4) =
        make_uint2(*(uint32_t*)&l01, *(uint32_t*)&l23);
}

// split 8 floats (cols sl*8..+7 of row r) into bf16 hi/lo images, 16B stores
__device__ __forceinline__ void split_store8(__nv_bfloat16* __restrict__ hi,
                                             __nv_bfloat16* __restrict__ lo,
                                             int r, int sl, const float* v) {
    uint4 ph, pl;
    uint32_t* phh = (uint32_t*)&ph;
    uint32_t* pll = (uint32_t*)&pl;
#pragma unroll
    for (int j = 0; j < 4; j++) {
        __nv_bfloat162 h2, l2;
        h2.x = __float2bfloat16(v[2 * j]);
        h2.y = __float2bfloat16(v[2 * j + 1]);
        l2.x = __float2bfloat16(v[2 * j]     - __bfloat162float(h2.x));
        l2.y = __float2bfloat16(v[2 * j + 1] - __bfloat162float(h2.y));
        phh[j] = *(uint32_t*)&h2;
        pll[j] = *(uint32_t*)&l2;
    }
    *(uint4*)(hi + (size_t)r * 128 + sl * 8) = ph;
    *(uint4*)(lo + (size_t)r * 128 + sl * 8) = pl;
}

// convert uint4 of 8 halves to 8 floats
__device__ __forceinline__ void cvt8(uint4 u, float* f) {
    __half2* h = (__half2*)&u;
#pragma unroll
    for (int j = 0; j < 4; j++) {
        float2 p = __half22float2(h[j]);
        f[2 * j] = p.x;
        f[2 * j + 1] = p.y;
    }
}

// ---------------- feats aggregation (fp32, warp per node, MODE 0) ----------
__global__ void agg_feats(const float* __restrict__ X,
                          const int* __restrict__ rowptr,
                          const int2* __restrict__ edge,
                          const float* __restrict__ dstn,
                          __nv_bfloat16* __restrict__ Ahi, __nv_bfloat16* __restrict__ Alo,
                          int n) {
    int warp = (blockIdx.x * blockDim.x + threadIdx.x) >> 5;
    int lane = threadIdx.x & 31;
    if (warp >= n) return;
    int beg = rowptr[warp];
    int end = rowptr[warp + 1];
    const float4* __restrict__ X4 = (const float4*)X;

    float4 aS = make_float4(0.f, 0.f, 0.f, 0.f);
    int e = beg;
    for (; e + 3 < end; e += 4) {
        int2 e0 = edge[e],     e1 = edge[e + 1];
        int2 e2 = edge[e + 2], e3 = edge[e + 3];
        float4 v0 = X4[e0.x * 32 + lane];
        float4 v1 = X4[e1.x * 32 + lane];
        float4 v2 = X4[e2.x * 32 + lane];
        float4 v3 = X4[e3.x * 32 + lane];
        float n0 = __int_as_float(e0.y), n1 = __int_as_float(e1.y);
        float n2 = __int_as_float(e2.y), n3 = __int_as_float(e3.y);
        aS.x += v0.x * n0 + v1.x * n1 + v2.x * n2 + v3.x * n3;
        aS.y += v0.y * n0 + v1.y * n1 + v2.y * n2 + v3.y * n3;
        aS.z += v0.z * n0 + v1.z * n1 + v2.z * n2 + v3.z * n3;
        aS.w += v0.w * n0 + v1.w * n1 + v2.w * n2 + v3.w * n3;
    }
    for (; e < end; e++) {
        int2 e0 = edge[e];
        float4 v0 = X4[e0.x * 32 + lane];
        float n0 = __int_as_float(e0.y);
        aS.x += v0.x * n0; aS.y += v0.y * n0; aS.z += v0.z * n0; aS.w += v0.w * n0;
    }
    float dn = dstn[warp];
    aS.x *= dn; aS.y *= dn; aS.z *= dn; aS.w *= dn;
    split_store(Ahi, Alo, warp, lane, aS);
}

// ---------------- fp16 aggregation (half-warp per node) ---------------------
// MODE 1: dual (A + F). MODE 2: F only.
template <int MODE>
__global__ void agg_h(const __half* __restrict__ X,
                      const int* __restrict__ rowptr,
                      const int2* __restrict__ edge,
                      const float* __restrict__ dstn,
                      __nv_bfloat16* __restrict__ Ahi, __nv_bfloat16* __restrict__ Alo,
                      __nv_bfloat16* __restrict__ Fhi, __nv_bfloat16* __restrict__ Flo,
                      int n) {
    int node = (blockIdx.x * blockDim.x + threadIdx.x) >> 4;   // half-warp per node
    int sl   = threadIdx.x & 15;
    if (node >= n) return;
    int beg = rowptr[node];
    int end = rowptr[node + 1];

    float aS[8], aP[8];
#pragma unroll
    for (int j = 0; j < 8; j++) { aS[j] = 0.f; aP[j] = 0.f; }

    int e = beg;
    for (; e + 3 < end; e += 4) {
        int2 e0 = edge[e],     e1 = edge[e + 1];
        int2 e2 = edge[e + 2], e3 = edge[e + 3];
        uint4 u0 = *(const uint4*)(X + (size_t)e0.x * 128 + sl * 8);
        uint4 u1 = *(const uint4*)(X + (size_t)e1.x * 128 + sl * 8);
        uint4 u2 = *(const uint4*)(X + (size_t)e2.x * 128 + sl * 8);
        uint4 u3 = *(const uint4*)(X + (size_t)e3.x * 128 + sl * 8);
        float f0[8], f1[8], f2[8], f3[8];
        cvt8(u0, f0); cvt8(u1, f1); cvt8(u2, f2); cvt8(u3, f3);
        if (MODE != 2) {
            float n0 = __int_as_float(e0.y), n1 = __int_as_float(e1.y);
            float n2 = __int_as_float(e2.y), n3 = __int_as_float(e3.y);
#pragma unroll
            for (int j = 0; j < 8; j++)
                aS[j] += f0[j] * n0 + f1[j] * n1 + f2[j] * n2 + f3[j] * n3;
        }
#pragma unroll
        for (int j = 0; j < 8; j++)
            aP[j] += f0[j] + f1[j] + f2[j] + f3[j];
    }
    for (; e < end; e++) {
        int2 e0 = edge[e];
        uint4 u0 = *(const uint4*)(X + (size_t)e0.x * 128 + sl * 8);
        float f0[8];
        cvt8(u0, f0);
        if (MODE != 2) {
            float n0 = __int_as_float(e0.y);
#pragma unroll
            for (int j = 0; j < 8; j++) aS[j] += f0[j] * n0;
        }
#pragma unroll
        for (int j = 0; j < 8; j++) aP[j] += f0[j];
    }
    if (MODE != 2) {
        float dn = dstn[node];
#pragma unroll
        for (int j = 0; j < 8; j++) aS[j] *= dn;
        split_store8(Ahi, Alo, node, sl, aS);
    }
    split_store8(Fhi, Flo, node, sl, aP);
}

// ---------------- WMMA GEMM, pure cp.async staging --------------------------
#define ALD 136
#define BLD 136
#define SM_AHI 0
#define SM_ALO 17408
#define SM_BHI 34816
#define SM_BLO 69632
#define SM_BIAS 104448
#define SM_TOT 112640

// MODE 0: H(fp16) = relu(v + bias) (dn folded into A);  MODE 1: C(fp32) = v + bias.
template <int MODE, int NSEG>
__global__ void __launch_bounds__(256, 2)
mma_gemm(const __nv_bfloat16* __restrict__ A0h, const __nv_bfloat16* __restrict__ A0l,
         const __nv_bfloat16* __restrict__ A1h, const __nv_bfloat16* __restrict__ A1l,
         const __nv_bfloat16* __restrict__ A2h, const __nv_bfloat16* __restrict__ A2l,
         const __nv_bfloat16* __restrict__ Bh0, const __nv_bfloat16* __restrict__ Bl0,
         const float* __restrict__ bias,
         __half* __restrict__ Hout, float* __restrict__ Cout, int n) {
    extern __shared__ unsigned char smem[];
    __nv_bfloat16* sAhi = (__nv_bfloat16*)(smem + SM_AHI);
    __nv_bfloat16* sAlo = (__nv_bfloat16*)(smem + SM_ALO);
    __nv_bfloat16* sBhi = (__nv_bfloat16*)(smem + SM_BHI);
    __nv_bfloat16* sBlo = (__nv_bfloat16*)(smem + SM_BLO);
    float*         sBias = (float*)(smem + SM_BIAS);

    const int tid  = threadIdx.x;
    const int wid  = tid >> 5;
    const int row0 = blockIdx.x * 64;

    const __nv_bfloat16* Ahs[3] = {A0h, A1h, A2h};
    const __nv_bfloat16* Als[3] = {A0l, A1l, A2l};

    const int rt = wid >> 1;
    const int ch = wid & 1;
    wmma::fragment<wmma::accumulator, 16, 16, 16, float> acc[4];

#pragma unroll
    for (int seg = 0; seg < NSEG; seg++) {
        if (seg > 0) __syncthreads();
        {
            const __nv_bfloat16* Ah = Ahs[seg];
            const __nv_bfloat16* Al = Als[seg];
#pragma unroll
            for (int i = 0; i < 4; i++) {
                int idx = i * 256 + tid;
                int r   = idx >> 4;
                int c16 = idx & 15;
                size_t g = (size_t)(row0 + r) * 128 + c16 * 8;
                __pipeline_memcpy_async(sAhi + r * ALD + c16 * 8, Ah + g, 16);
                __pipeline_memcpy_async(sAlo + r * ALD + c16 * 8, Al + g, 16);
            }
        }
        {
            const __nv_bfloat16* Bh = Bh0 + seg * DD * DD;
            const __nv_bfloat16* Bl = Bl0 + seg * DD * DD;
#pragma unroll
            for (int i = 0; i < 8; i++) {
                int idx = i * 256 + tid;
                int r   = idx >> 4;
                int c16 = idx & 15;
                __pipeline_memcpy_async(sBhi + r * BLD + c16 * 8, Bh + r * 128 + c16 * 8, 16);
                __pipeline_memcpy_async(sBlo + r * BLD + c16 * 8, Bl + r * 128 + c16 * 8, 16);
            }
        }
        __pipeline_commit();
        if (seg == 0) {
            for (int idx = tid; idx < 2048; idx += 256)
                sBias[idx] = bias[(idx >> 8) * 16 + (idx & 15)];
        }
        __pipeline_wait_prior(0);
        __syncthreads();

        if (seg == 0) {
#pragma unroll
            for (int j = 0; j < 4; j++)
                wmma::load_matrix_sync(acc[j], sBias + (ch * 4 + j) * 256, 16,
                                       wmma::mem_row_major);
        }

#pragma unroll
        for (int kk = 0; kk < 8; kk++) {
            wmma::fragment<wmma::matrix_a, 16, 16, 16, __nv_bfloat16, wmma::row_major> ah, al;
            wmma::load_matrix_sync(ah, sAhi + (rt * 16) * ALD + kk * 16, ALD);
            wmma::load_matrix_sync(al, sAlo + (rt * 16) * ALD + kk * 16, ALD);
#pragma unroll
            for (int j = 0; j < 4; j++) {
                int nt = ch * 4 + j;
                wmma::fragment<wmma::matrix_b, 16, 16, 16, __nv_bfloat16, wmma::row_major> bh, bl;
                wmma::load_matrix_sync(bh, sBhi + (kk * 16) * BLD + nt * 16, BLD);
                wmma::load_matrix_sync(bl, sBlo + (kk * 16) * BLD + nt * 16, BLD);
                wmma::mma_sync(acc[j], ah, bh, acc[j]);
                wmma::mma_sync(acc[j], ah, bl, acc[j]);
                wmma::mma_sync(acc[j], al, bh, acc[j]);
            }
        }
    }

    if (MODE == 1) {
        if (row0 + rt * 16 + 16 <= n) {
#pragma unroll
            for (int j = 0; j < 4; j++)
                wmma::store_matrix_sync(Cout + (size_t)(row0 + rt * 16) * 128 + (ch * 4 + j) * 16,
                                        acc[j], 128, wmma::mem_row_major);
        }
    } else {
        __syncthreads();
        float* smemF = (float*)(smem + SM_AHI);   // 64*128*4 = 32KB
        if (row0 + rt * 16 + 16 <= n) {
#pragma unroll
            for (int j = 0; j < 4; j++) {
#pragma unroll
                for (int i = 0; i < acc[j].num_elements; i++)
                    acc[j].x[i] = fmaxf(acc[j].x[i], 0.f);
                wmma::store_matrix_sync(smemF + (rt * 16) * 128 + (ch * 4 + j) * 16,
                                        acc[j], 128, wmma::mem_row_major);
            }
        }
        __syncthreads();
#pragma unroll
        for (int i = 0; i < 8; i++) {
            int idx4 = i * 256 + tid;
            int r    = idx4 >> 5;
            int c4   = idx4 & 31;
            if (row0 + r < n) {
                float4 v = ((const float4*)smemF)[idx4];
                __half2 p0 = __floats2half2_rn(v.x, v.y);
                __half2 p1 = __floats2half2_rn(v.z, v.w);
                *(uint2*)(Hout + (size_t)(row0 + r) * 128 + c4 * 4) =
                    make_uint2(*(uint32_t*)&p0, *(uint32_t*)&p1);
            }
        }
    }
}

// ---------------------------------------------------------------------------
extern "C" void kernel_launch(void* const* d_in, const int* in_sizes, int n_in,
                              void* d_out, int out_size) {
    const float* feats = (const float*)d_in[0];
    const int*   src   = (const int*)  d_in[1];
    const int*   dst   = (const int*)  d_in[2];
    const float* W0    = (const float*)d_in[3];
    const float* b0    = (const float*)d_in[4];
    const float* W1    = (const float*)d_in[5];
    const float* b1    = (const float*)d_in[6];
    const float* W2    = (const float*)d_in[7];
    const float* b2    = (const float*)d_in[8];
    const float* Wout  = (const float*)d_in[9];
    const float* bout  = (const float*)d_in[10];
    float*       out   = (float*)d_out;

    const int n = in_sizes[0] / DD;
    const int e = in_sizes[1];

    __half *h0, *h1, *h2;
    float *srcn, *dstn;
    int *outdeg, *indeg, *rowptr, *cursor, *bsum;
    int2 *edge;
    __nv_bfloat16 *Ahi, *Alo, *Fhi, *Flo, *Bhi, *Blo;
    cudaGetSymbolAddress((void**)&h0,     g_h0);
    cudaGetSymbolAddress((void**)&h1,     g_h1);
    cudaGetSymbolAddress((void**)&h2,     g_h2);
    cudaGetSymbolAddress((void**)&Ahi,    g_Ahi);
    cudaGetSymbolAddress((void**)&Alo,    g_Alo);
    cudaGetSymbolAddress((void**)&Fhi,    g_Fhi);
    cudaGetSymbolAddress((void**)&Flo,    g_Flo);
    cudaGetSymbolAddress((void**)&srcn,   g_srcn);
    cudaGetSymbolAddress((void**)&dstn,   g_dstn);
    cudaGetSymbolAddress((void**)&outdeg, g_outdeg);
    cudaGetSymbolAddress((void**)&indeg,  g_indeg);
    cudaGetSymbolAddress((void**)&rowptr, g_rowptr);
    cudaGetSymbolAddress((void**)&cursor, g_cursor);
    cudaGetSymbolAddress((void**)&edge,   g_edge);
    cudaGetSymbolAddress((void**)&bsum,   g_bsum);
    cudaGetSymbolAddress((void**)&Bhi,    g_Bhi);
    cudaGetSymbolAddress((void**)&Blo,    g_Blo);

    const int nbN   = (n + 255) / 256;
    const int nbE   = (e + 255) / 256;
    const int nbAg  = (n + 7) / 8;       // warp per node (feats)
    const int nbAgH = (n + 15) / 16;     // half-warp per node (fp16)
    const int nbT   = (n + 63) / 64;

    cudaFuncSetAttribute(mma_gemm<0, 1>, cudaFuncAttributeMaxDynamicSharedMemorySize, SM_TOT);
    cudaFuncSetAttribute(mma_gemm<1, 3>, cudaFuncAttributeMaxDynamicSharedMemorySize, SM_TOT);

    // ---- CSR build + norms + weight conversion ----
    zero_ints      <<<nbN, 256>>>(outdeg, indeg, n);
    conv_w         <<<(6 * DD * DD + 255) / 256, 256>>>(W0, W1, W2, Wout, Bhi, Blo);
    deg_hist       <<<nbE, 256>>>(src, dst, outdeg, indeg, e);
    scan_block_sums<<<nbN, 256>>>(indeg, bsum, n);
    scan_bsums     <<<1,   256>>>(bsum, nbN);
    scan_final     <<<nbN, 256>>>(indeg, bsum, outdeg, rowptr, cursor, srcn, dstn, n, e);
    scatter_edges  <<<nbE, 256>>>(src, dst, srcn, cursor, edge, e);

    // ---- layer 1 (feats fp32, warp per node) ----
    agg_feats<<<nbAg, 256>>>(feats, rowptr, edge, dstn, Ahi, Alo, n);
    mma_gemm<0, 1><<<nbT, 256, SM_TOT>>>(Ahi, Alo, nullptr, nullptr, nullptr, nullptr,
                                         Bhi + 0 * DD * DD, Blo + 0 * DD * DD,
                                         b0, h0, nullptr, n);
    // ---- layer 2 (+ F0), h0 fp16, half-warp per node ----
    agg_h<1><<<nbAgH, 256>>>(h0, rowptr, edge, dstn,
                             Ahi, Alo, Fhi + 0 * NPAD * DD, Flo + 0 * NPAD * DD, n);
    mma_gemm<0, 1><<<nbT, 256, SM_TOT>>>(Ahi, Alo, nullptr, nullptr, nullptr, nullptr,
                                         Bhi + 1 * DD * DD, Blo + 1 * DD * DD,
                                         b1, h1, nullptr, n);
    // ---- layer 3 (+ F1), h1 fp16 ----
    agg_h<1><<<nbAgH, 256>>>(h1, rowptr, edge, dstn,
                             Ahi, Alo, Fhi + 1 * NPAD * DD, Flo + 1 * NPAD * DD, n);
    mma_gemm<0, 1><<<nbT, 256, SM_TOT>>>(Ahi, Alo, nullptr, nullptr, nullptr, nullptr,
                                         Bhi + 2 * DD * DD, Blo + 2 * DD * DD,
                                         b2, h2, nullptr, n);
    // ---- F2 = plain agg(h2) ----
    agg_h<2><<<nbAgH, 256>>>(h2, rowptr, edge, dstn,
                             nullptr, nullptr,
                             Fhi + 2 * NPAD * DD, Flo + 2 * NPAD * DD, n);
    // ---- out = [F0 F1 F2] @ Wout + bout ----
    mma_gemm<1, 3><<<nbT, 256, SM_TOT>>>(Fhi + 0 * NPAD * DD, Flo + 0 * NPAD * DD,
                                         Fhi + 1 * NPAD * DD, Flo + 1 * NPAD * DD,
                                         Fhi + 2 * NPAD * DD, Flo + 2 * NPAD * DD,
                                         Bhi + 3 * DD * DD, Blo + 3 * DD * DD,
                                         bout, nullptr, out, n);
}

// round 14
// speedup vs baseline: 1.3314x; 1.0060x over previous
#include <cuda_runtime.h>
#include <cuda_bf16.h>
#include <cuda_fp16.h>
#include <mma.h>
#include <cuda_pipeline.h>
#include <cstdint>

using namespace nvcuda;

// ---------------------------------------------------------------------------
// JKNet R14: R13 + (1) feats pre-converted to fp16 and routed through the
// half-warp gather path, (2) 8-edge main unroll in agg_h (MLP 4->8),
// (3) fused input-conversion kernel. GEMM path unchanged.
// ---------------------------------------------------------------------------

#define NN 50000
#define EE 800000
#define DD 128
#define NPAD (NN + 64)

// ---------------- scratch ---------------------------------------------------
__device__ __half g_hf[NN * DD];        // fp16 feats
__device__ __half g_h0[NN * DD];
__device__ __half g_h1[NN * DD];
__device__ __half g_h2[NN * DD];
__device__ __nv_bfloat16 g_Ahi[NPAD * DD];
__device__ __nv_bfloat16 g_Alo[NPAD * DD];
__device__ __nv_bfloat16 g_Fhi[3][NPAD * DD];
__device__ __nv_bfloat16 g_Flo[3][NPAD * DD];
__device__ float g_srcn[NN];
__device__ float g_dstn[NN];
__device__ int   g_outdeg[NN];
__device__ int   g_indeg [NN];
__device__ int   g_rowptr[NN + 1];
__device__ int   g_cursor[NN];
__device__ int2  g_edge[EE];            // (src, srcn bits)
__device__ int   g_bsum[256];
__device__ __nv_bfloat16 g_Bhi[6 * DD * DD];
__device__ __nv_bfloat16 g_Blo[6 * DD * DD];

// ---------------- CSR build -------------------------------------------------
__global__ void zero_ints(int* __restrict__ a, int* __restrict__ b, int n) {
    int i = blockIdx.x * blockDim.x + threadIdx.x;
    if (i < n) { a[i] = 0; b[i] = 0; }
}
__global__ void deg_hist(const int* __restrict__ src, const int* __restrict__ dst,
                         int* __restrict__ outdeg, int* __restrict__ indeg, int e) {
    int i = blockIdx.x * blockDim.x + threadIdx.x;
    if (i < e) { atomicAdd(&outdeg[src[i]], 1); atomicAdd(&indeg[dst[i]], 1); }
}
__global__ void scan_block_sums(const int* __restrict__ deg, int* __restrict__ bsum, int n) {
    __shared__ int s[256];
    int i = blockIdx.x * 256 + threadIdx.x;
    s[threadIdx.x] = (i < n) ? deg[i] : 0;
    __syncthreads();
    for (int off = 128; off > 0; off >>= 1) {
        if (threadIdx.x < off) s[threadIdx.x] += s[threadIdx.x + off];
        __syncthreads();
    }
    if (threadIdx.x == 0) bsum[blockIdx.x] = s[0];
}
__global__ void scan_bsums(int* __restrict__ bsum, int nb) {
    __shared__ int s[256];
    int t = threadIdx.x;
    int v = (t < nb) ? bsum[t] : 0;
    s[t] = v;
    __syncthreads();
    for (int off = 1; off < 256; off <<= 1) {
        int add = (t >= off) ? s[t - off] : 0;
        __syncthreads();
        s[t] += add;
        __syncthreads();
    }
    if (t < nb) bsum[t] = s[t] - v;
}
__global__ void scan_final(const int* __restrict__ deg, const int* __restrict__ bsum,
                           const int* __restrict__ outdeg,
                           int* __restrict__ rowptr, int* __restrict__ cursor,
                           float* __restrict__ sn, float* __restrict__ dn,
                           int n, int etot) {
    __shared__ int s[256];
    int t = threadIdx.x;
    int i = blockIdx.x * 256 + t;
    int v = (i < n) ? deg[i] : 0;
    s[t] = v;
    __syncthreads();
    for (int off = 1; off < 256; off <<= 1) {
        int add = (t >= off) ? s[t - off] : 0;
        __syncthreads();
        s[t] += add;
        __syncthreads();
    }
    int ex = bsum[blockIdx.x] + s[t] - v;
    if (i < n) {
        rowptr[i] = ex;
        cursor[i] = ex;
        sn[i] = rsqrtf((float)max(outdeg[i], 1));
        dn[i] = rsqrtf((float)max(v, 1));
    }
    if (i == 0) rowptr[n] = etot;
}
__global__ void scatter_edges(const int* __restrict__ src, const int* __restrict__ dst,
                              const float* __restrict__ srcn,
                              int* __restrict__ cursor, int2* __restrict__ edge, int e) {
    int i = blockIdx.x * blockDim.x + threadIdx.x;
    if (i < e) {
        int s = src[i];
        int p = atomicAdd(&cursor[dst[i]], 1);
        edge[p] = make_int2(s, __float_as_int(srcn[s]));
    }
}

// ---------------- input conversion: feats -> fp16, W -> bf16 hi/lo ----------
__global__ void conv_inputs(const float* __restrict__ feats,
                            const float* __restrict__ W0, const float* __restrict__ W1,
                            const float* __restrict__ W2, const float* __restrict__ Wout,
                            __half* __restrict__ hf,
                            __nv_bfloat16* __restrict__ hi, __nv_bfloat16* __restrict__ lo,
                            int nfeat4) {
    int idx = blockIdx.x * blockDim.x + threadIdx.x;
    if (idx < nfeat4) {
        float4 v = ((const float4*)feats)[idx];
        __half2 p0 = __floats2half2_rn(v.x, v.y);
        __half2 p1 = __floats2half2_rn(v.z, v.w);
        *(uint2*)(hf + (size_t)idx * 4) = make_uint2(*(uint32_t*)&p0, *(uint32_t*)&p1);
    }
    if (idx < 6 * DD * DD) {
        int m = idx / (DD * DD);
        int rem = idx % (DD * DD);
        const float* src = (m == 0) ? W0 : (m == 1) ? W1 : (m == 2) ? W2
                                         : (Wout + (m - 3) * DD * DD);
        float v = src[rem];
        __nv_bfloat16 h = __float2bfloat16(v);
        __nv_bfloat16 l = __float2bfloat16(v - __bfloat162float(h));
        hi[idx] = h;
        lo[idx] = l;
    }
}

// split 8 floats (cols sl*8..+7 of row r) into bf16 hi/lo images, 16B stores
__device__ __forceinline__ void split_store8(__nv_bfloat16* __restrict__ hi,
                                             __nv_bfloat16* __restrict__ lo,
                                             int r, int sl, const float* v) {
    uint4 ph, pl;
    uint32_t* phh = (uint32_t*)&ph;
    uint32_t* pll = (uint32_t*)&pl;
#pragma unroll
    for (int j = 0; j < 4; j++) {
        __nv_bfloat162 h2, l2;
        h2.x = __float2bfloat16(v[2 * j]);
        h2.y = __float2bfloat16(v[2 * j + 1]);
        l2.x = __float2bfloat16(v[2 * j]     - __bfloat162float(h2.x));
        l2.y = __float2bfloat16(v[2 * j + 1] - __bfloat162float(h2.y));
        phh[j] = *(uint32_t*)&h2;
        pll[j] = *(uint32_t*)&l2;
    }
    *(uint4*)(hi + (size_t)r * 128 + sl * 8) = ph;
    *(uint4*)(lo + (size_t)r * 128 + sl * 8) = pl;
}

// convert uint4 of 8 halves to 8 floats
__device__ __forceinline__ void cvt8(uint4 u, float* f) {
    __half2* h = (__half2*)&u;
#pragma unroll
    for (int j = 0; j < 4; j++) {
        float2 p = __half22float2(h[j]);
        f[2 * j] = p.x;
        f[2 * j + 1] = p.y;
    }
}

// ---------------- fp16 aggregation (half-warp per node) ---------------------
// MODE 0: A only. MODE 1: dual (A + F). MODE 2: F only.
template <int MODE>
__global__ void agg_h(const __half* __restrict__ X,
                      const int* __restrict__ rowptr,
                      const int2* __restrict__ edge,
                      const float* __restrict__ dstn,
                      __nv_bfloat16* __restrict__ Ahi, __nv_bfloat16* __restrict__ Alo,
                      __nv_bfloat16* __restrict__ Fhi, __nv_bfloat16* __restrict__ Flo,
                      int n) {
    int node = (blockIdx.x * blockDim.x + threadIdx.x) >> 4;   // half-warp per node
    int sl   = threadIdx.x & 15;
    if (node >= n) return;
    int beg = rowptr[node];
    int end = rowptr[node + 1];

    float aS[8], aP[8];
#pragma unroll
    for (int j = 0; j < 8; j++) { aS[j] = 0.f; aP[j] = 0.f; }

    int e = beg;
    // 8-edge main stage: 8 independent 16B loads in flight per thread
    for (; e + 7 < end; e += 8) {
        int2 ed[8];
#pragma unroll
        for (int t = 0; t < 8; t++) ed[t] = edge[e + t];
        uint4 u[8];
#pragma unroll
        for (int t = 0; t < 8; t++)
            u[t] = *(const uint4*)(X + (size_t)ed[t].x * 128 + sl * 8);
#pragma unroll
        for (int t = 0; t < 8; t++) {
            float f[8];
            cvt8(u[t], f);
            if (MODE != 2) {
                float nv = __int_as_float(ed[t].y);
#pragma unroll
                for (int j = 0; j < 8; j++) aS[j] += f[j] * nv;
            }
            if (MODE != 0) {
#pragma unroll
                for (int j = 0; j < 8; j++) aP[j] += f[j];
            }
        }
    }
    for (; e + 3 < end; e += 4) {
        int2 ed[4];
#pragma unroll
        for (int t = 0; t < 4; t++) ed[t] = edge[e + t];
        uint4 u[4];
#pragma unroll
        for (int t = 0; t < 4; t++)
            u[t] = *(const uint4*)(X + (size_t)ed[t].x * 128 + sl * 8);
#pragma unroll
        for (int t = 0; t < 4; t++) {
            float f[8];
            cvt8(u[t], f);
            if (MODE != 2) {
                float nv = __int_as_float(ed[t].y);
#pragma unroll
                for (int j = 0; j < 8; j++) aS[j] += f[j] * nv;
            }
            if (MODE != 0) {
#pragma unroll
                for (int j = 0; j < 8; j++) aP[j] += f[j];
            }
        }
    }
    for (; e < end; e++) {
        int2 e0 = edge[e];
        uint4 u0 = *(const uint4*)(X + (size_t)e0.x * 128 + sl * 8);
        float f0[8];
        cvt8(u0, f0);
        if (MODE != 2) {
            float n0 = __int_as_float(e0.y);
#pragma unroll
            for (int j = 0; j < 8; j++) aS[j] += f0[j] * n0;
        }
        if (MODE != 0) {
#pragma unroll
            for (int j = 0; j < 8; j++) aP[j] += f0[j];
        }
    }
    if (MODE != 2) {
        float dn = dstn[node];
#pragma unroll
        for (int j = 0; j < 8; j++) aS[j] *= dn;
        split_store8(Ahi, Alo, node, sl, aS);
    }
    if (MODE != 0) split_store8(Fhi, Flo, node, sl, aP);
}

// ---------------- WMMA GEMM, pure cp.async staging --------------------------
#define ALD 136
#define BLD 136
#define SM_AHI 0
#define SM_ALO 17408
#define SM_BHI 34816
#define SM_BLO 69632
#define SM_BIAS 104448
#define SM_TOT 112640

// MODE 0: H(fp16) = relu(v + bias) (dn folded into A);  MODE 1: C(fp32) = v + bias.
template <int MODE, int NSEG>
__global__ void __launch_bounds__(256, 2)
mma_gemm(const __nv_bfloat16* __restrict__ A0h, const __nv_bfloat16* __restrict__ A0l,
         const __nv_bfloat16* __restrict__ A1h, const __nv_bfloat16* __restrict__ A1l,
         const __nv_bfloat16* __restrict__ A2h, const __nv_bfloat16* __restrict__ A2l,
         const __nv_bfloat16* __restrict__ Bh0, const __nv_bfloat16* __restrict__ Bl0,
         const float* __restrict__ bias,
         __half* __restrict__ Hout, float* __restrict__ Cout, int n) {
    extern __shared__ unsigned char smem[];
    __nv_bfloat16* sAhi = (__nv_bfloat16*)(smem + SM_AHI);
    __nv_bfloat16* sAlo = (__nv_bfloat16*)(smem + SM_ALO);
    __nv_bfloat16* sBhi = (__nv_bfloat16*)(smem + SM_BHI);
    __nv_bfloat16* sBlo = (__nv_bfloat16*)(smem + SM_BLO);
    float*         sBias = (float*)(smem + SM_BIAS);

    const int tid  = threadIdx.x;
    const int wid  = tid >> 5;
    const int row0 = blockIdx.x * 64;

    const __nv_bfloat16* Ahs[3] = {A0h, A1h, A2h};
    const __nv_bfloat16* Als[3] = {A0l, A1l, A2l};

    const int rt = wid >> 1;
    const int ch = wid & 1;
    wmma::fragment<wmma::accumulator, 16, 16, 16, float> acc[4];

#pragma unroll
    for (int seg = 0; seg < NSEG; seg++) {
        if (seg > 0) __syncthreads();
        {
            const __nv_bfloat16* Ah = Ahs[seg];
            const __nv_bfloat16* Al = Als[seg];
#pragma unroll
            for (int i = 0; i < 4; i++) {
                int idx = i * 256 + tid;
                int r   = idx >> 4;
                int c16 = idx & 15;
                size_t g = (size_t)(row0 + r) * 128 + c16 * 8;
                __pipeline_memcpy_async(sAhi + r * ALD + c16 * 8, Ah + g, 16);
                __pipeline_memcpy_async(sAlo + r * ALD + c16 * 8, Al + g, 16);
            }
        }
        {
            const __nv_bfloat16* Bh = Bh0 + seg * DD * DD;
            const __nv_bfloat16* Bl = Bl0 + seg * DD * DD;
#pragma unroll
            for (int i = 0; i < 8; i++) {
                int idx = i * 256 + tid;
                int r   = idx >> 4;
                int c16 = idx & 15;
                __pipeline_memcpy_async(sBhi + r * BLD + c16 * 8, Bh + r * 128 + c16 * 8, 16);
                __pipeline_memcpy_async(sBlo + r * BLD + c16 * 8, Bl + r * 128 + c16 * 8, 16);
            }
        }
        __pipeline_commit();
        if (seg == 0) {
            for (int idx = tid; idx < 2048; idx += 256)
                sBias[idx] = bias[(idx >> 8) * 16 + (idx & 15)];
        }
        __pipeline_wait_prior(0);
        __syncthreads();

        if (seg == 0) {
#pragma unroll
            for (int j = 0; j < 4; j++)
                wmma::load_matrix_sync(acc[j], sBias + (ch * 4 + j) * 256, 16,
                                       wmma::mem_row_major);
        }

#pragma unroll
        for (int kk = 0; kk < 8; kk++) {
            wmma::fragment<wmma::matrix_a, 16, 16, 16, __nv_bfloat16, wmma::row_major> ah, al;
            wmma::load_matrix_sync(ah, sAhi + (rt * 16) * ALD + kk * 16, ALD);
            wmma::load_matrix_sync(al, sAlo + (rt * 16) * ALD + kk * 16, ALD);
#pragma unroll
            for (int j = 0; j < 4; j++) {
                int nt = ch * 4 + j;
                wmma::fragment<wmma::matrix_b, 16, 16, 16, __nv_bfloat16, wmma::row_major> bh, bl;
                wmma::load_matrix_sync(bh, sBhi + (kk * 16) * BLD + nt * 16, BLD);
                wmma::load_matrix_sync(bl, sBlo + (kk * 16) * BLD + nt * 16, BLD);
                wmma::mma_sync(acc[j], ah, bh, acc[j]);
                wmma::mma_sync(acc[j], ah, bl, acc[j]);
                wmma::mma_sync(acc[j], al, bh, acc[j]);
            }
        }
    }

    if (MODE == 1) {
        if (row0 + rt * 16 + 16 <= n) {
#pragma unroll
            for (int j = 0; j < 4; j++)
                wmma::store_matrix_sync(Cout + (size_t)(row0 + rt * 16) * 128 + (ch * 4 + j) * 16,
                                        acc[j], 128, wmma::mem_row_major);
        }
    } else {
        __syncthreads();
        float* smemF = (float*)(smem + SM_AHI);   // 64*128*4 = 32KB
        if (row0 + rt * 16 + 16 <= n) {
#pragma unroll
            for (int j = 0; j < 4; j++) {
#pragma unroll
                for (int i = 0; i < acc[j].num_elements; i++)
                    acc[j].x[i] = fmaxf(acc[j].x[i], 0.f);
                wmma::store_matrix_sync(smemF + (rt * 16) * 128 + (ch * 4 + j) * 16,
                                        acc[j], 128, wmma::mem_row_major);
            }
        }
        __syncthreads();
#pragma unroll
        for (int i = 0; i < 8; i++) {
            int idx4 = i * 256 + tid;
            int r    = idx4 >> 5;
            int c4   = idx4 & 31;
            if (row0 + r < n) {
                float4 v = ((const float4*)smemF)[idx4];
                __half2 p0 = __floats2half2_rn(v.x, v.y);
                __half2 p1 = __floats2half2_rn(v.z, v.w);
                *(uint2*)(Hout + (size_t)(row0 + r) * 128 + c4 * 4) =
                    make_uint2(*(uint32_t*)&p0, *(uint32_t*)&p1);
            }
        }
    }
}

// ---------------------------------------------------------------------------
extern "C" void kernel_launch(void* const* d_in, const int* in_sizes, int n_in,
                              void* d_out, int out_size) {
    const float* feats = (const float*)d_in[0];
    const int*   src   = (const int*)  d_in[1];
    const int*   dst   = (const int*)  d_in[2];
    const float* W0    = (const float*)d_in[3];
    const float* b0    = (const float*)d_in[4];
    const float* W1    = (const float*)d_in[5];
    const float* b1    = (const float*)d_in[6];
    const float* W2    = (const float*)d_in[7];
    const float* b2    = (const float*)d_in[8];
    const float* Wout  = (const float*)d_in[9];
    const float* bout  = (const float*)d_in[10];
    float*       out   = (float*)d_out;

    const int n = in_sizes[0] / DD;
    const int e = in_sizes[1];

    __half *hf, *h0, *h1, *h2;
    float *srcn, *dstn;
    int *outdeg, *indeg, *rowptr, *cursor, *bsum;
    int2 *edge;
    __nv_bfloat16 *Ahi, *Alo, *Fhi, *Flo, *Bhi, *Blo;
    cudaGetSymbolAddress((void**)&hf,     g_hf);
    cudaGetSymbolAddress((void**)&h0,     g_h0);
    cudaGetSymbolAddress((void**)&h1,     g_h1);
    cudaGetSymbolAddress((void**)&h2,     g_h2);
    cudaGetSymbolAddress((void**)&Ahi,    g_Ahi);
    cudaGetSymbolAddress((void**)&Alo,    g_Alo);
    cudaGetSymbolAddress((void**)&Fhi,    g_Fhi);
    cudaGetSymbolAddress((void**)&Flo,    g_Flo);
    cudaGetSymbolAddress((void**)&srcn,   g_srcn);
    cudaGetSymbolAddress((void**)&dstn,   g_dstn);
    cudaGetSymbolAddress((void**)&outdeg, g_outdeg);
    cudaGetSymbolAddress((void**)&indeg,  g_indeg);
    cudaGetSymbolAddress((void**)&rowptr, g_rowptr);
    cudaGetSymbolAddress((void**)&cursor, g_cursor);
    cudaGetSymbolAddress((void**)&edge,   g_edge);
    cudaGetSymbolAddress((void**)&bsum,   g_bsum);
    cudaGetSymbolAddress((void**)&Bhi,    g_Bhi);
    cudaGetSymbolAddress((void**)&Blo,    g_Blo);

    const int nbN   = (n + 255) / 256;
    const int nbE   = (e + 255) / 256;
    const int nbAgH = (n + 15) / 16;     // half-warp per node
    const int nbT   = (n + 63) / 64;
    const int nfeat4 = n * DD / 4;       // 1.6M float4s
    const int nbCv  = (nfeat4 + 255) / 256;

    cudaFuncSetAttribute(mma_gemm<0, 1>, cudaFuncAttributeMaxDynamicSharedMemorySize, SM_TOT);
    cudaFuncSetAttribute(mma_gemm<1, 3>, cudaFuncAttributeMaxDynamicSharedMemorySize, SM_TOT);

    // ---- CSR build + norms + input conversion ----
    zero_ints      <<<nbN, 256>>>(outdeg, indeg, n);
    conv_inputs    <<<nbCv, 256>>>(feats, W0, W1, W2, Wout, hf, Bhi, Blo, nfeat4);
    deg_hist       <<<nbE, 256>>>(src, dst, outdeg, indeg, e);
    scan_block_sums<<<nbN, 256>>>(indeg, bsum, n);
    scan_bsums     <<<1,   256>>>(bsum, nbN);
    scan_final     <<<nbN, 256>>>(indeg, bsum, outdeg, rowptr, cursor, srcn, dstn, n, e);
    scatter_edges  <<<nbE, 256>>>(src, dst, srcn, cursor, edge, e);

    // ---- layer 1 (feats fp16, half-warp per node) ----
    agg_h<0><<<nbAgH, 256>>>(hf, rowptr, edge, dstn, Ahi, Alo, nullptr, nullptr, n);
    mma_gemm<0, 1><<<nbT, 256, SM_TOT>>>(Ahi, Alo, nullptr, nullptr, nullptr, nullptr,
                                         Bhi + 0 * DD * DD, Blo + 0 * DD * DD,
                                         b0, h0, nullptr, n);
    // ---- layer 2 (+ F0) ----
    agg_h<1><<<nbAgH, 256>>>(h0, rowptr, edge, dstn,
                             Ahi, Alo, Fhi + 0 * NPAD * DD, Flo + 0 * NPAD * DD, n);
    mma_gemm<0, 1><<<nbT, 256, SM_TOT>>>(Ahi, Alo, nullptr, nullptr, nullptr, nullptr,
                                         Bhi + 1 * DD * DD, Blo + 1 * DD * DD,
                                         b1, h1, nullptr, n);
    // ---- layer 3 (+ F1) ----
    agg_h<1><<<nbAgH, 256>>>(h1, rowptr, edge, dstn,
                             Ahi, Alo, Fhi + 1 * NPAD * DD, Flo + 1 * NPAD * DD, n);
    mma_gemm<0, 1><<<nbT, 256, SM_TOT>>>(Ahi, Alo, nullptr, nullptr, nullptr, nullptr,
                                         Bhi + 2 * DD * DD, Blo + 2 * DD * DD,
                                         b2, h2, nullptr, n);
    // ---- F2 = plain agg(h2) ----
    agg_h<2><<<nbAgH, 256>>>(h2, rowptr, edge, dstn,
                             nullptr, nullptr,
                             Fhi + 2 * NPAD * DD, Flo + 2 * NPAD * DD, n);
    // ---- out = [F0 F1 F2] @ Wout + bout ----
    mma_gemm<1, 3><<<nbT, 256, SM_TOT>>>(Fhi + 0 * NPAD * DD, Flo + 0 * NPAD * DD,
                                         Fhi + 1 * NPAD * DD, Flo + 1 * NPAD * DD,
                                         Fhi + 2 * NPAD * DD, Flo + 2 * NPAD * DD,
                                         Bhi + 3 * DD * DD, Blo + 3 * DD * DD,
                                         bout, nullptr, out, n);
}